// round 13
// baseline (speedup 1.0000x reference)
#include <cuda_runtime.h>
#include <cuda_bf16.h>
#include <math.h>
#include <stdint.h>

// ===================== asm helpers =====================
__device__ __forceinline__ uint32_t smem_u32(const void* p) {
    uint32_t a;
    asm("{ .reg .u64 t; cvta.to.shared.u64 t, %1; cvt.u32.u64 %0, t; }" : "=r"(a) : "l"(p));
    return a;
}
#define CP16(dst_u32, src_ptr) \
    asm volatile("cp.async.cg.shared.global [%0], [%1], 16;" :: "r"(dst_u32), "l"(src_ptr) : "memory")
#define CP_COMMIT() asm volatile("cp.async.commit_group;" ::: "memory")
#define CP_WAIT(n)  asm volatile("cp.async.wait_group %0;" :: "n"(n) : "memory")

#define MMA(d, a0, a1, a2, a3, b0, b1) \
    asm("mma.sync.aligned.m16n8k16.row.col.f32.bf16.bf16.f32 " \
        "{%0,%1,%2,%3}, {%4,%5,%6,%7}, {%8,%9}, {%0,%1,%2,%3};" \
        : "+f"((d)[0]), "+f"((d)[1]), "+f"((d)[2]), "+f"((d)[3]) \
        : "r"(a0), "r"(a1), "r"(a2), "r"(a3), "r"(b0), "r"(b1))

// ===================== smem layout (persistent) =====================
#define SM_P2    0          // 131072  W2 fragments (resident)
#define SM_P3    131072     // 8192    W3 fragments (resident)
#define SM_ACT   139264     // 65536   per-ray region (phases alias):
                            //  A: P1(0..32768) | XF(32768..49152)
                            //  B: H1F (0..65536)
                            //  C: GEOS(49152..57600) | ACC3(57600..60160) | (XF_next 32768..49152, P1_next 0..32768)
#define SM_B1    204800     // 1024
#define SM_B2    205824     // 1024
#define SM_B3    206848     // 64
#define SM_DIR   206912     // 128
#define SM_COMP  207040     // 2048
#define SM_BC2   209088     // 16
#define SM_WC1   209104     // 10752 (resident)
#define SM_WC2   219856     // 768
#define SM_BC1   220624     // 256
#define SM_DIRC  220880     // 256   dircontrib[64]
#define SMEM_BYTES 221136

#define ACT_XF    32768
#define ACT_GEOS  49152     // [16][132] fp32 transposed, 8448 B
#define ACT_ACC3  57600     // [128][5] fp32 (stride 5 -> conflict-free atomics), 2560 B
#define ZERO_FLOATS 2752    // GEOS (2112) + ACC3 (640), contiguous from ACT_GEOS

// packed weight image (bf16 fragment order, uint4-paired): P1 32KB | P2 128KB | P3 8KB
__device__ __align__(128) uint32_t g_pack[43008];

__device__ __forceinline__ uint32_t bf16_pack2(float x, float y) {
    __nv_bfloat16 hx = __float2bfloat16(x), hy = __float2bfloat16(y);
    return (uint32_t)__bfloat16_as_ushort(hx) | ((uint32_t)__bfloat16_as_ushort(hy) << 16);
}
__device__ __forceinline__ void sts_bf16(uint32_t addr, float v) {
    uint16_t u = __bfloat16_as_ushort(__float2bfloat16(v));
    asm volatile("st.shared.u16 [%0], %1;" :: "r"(addr), "h"(u));
}
__device__ __forceinline__ void sincos_fast(float phi, float* s, float* c) {
    float k = rintf(phi * 0.15915494309f);
    float r = fmaf(-k, 6.2831854820251465f, phi);
    r = fmaf(-k, -1.7484556000744263e-07f, r);
    *s = __sinf(r);
    *c = __cosf(r);
}

// byte address (relative) of feature j of sample m inside an A-fragment array
__device__ __forceinline__ uint32_t xf_addr(int m, int j) {
    int p = j >> 1;
    int kt = p >> 3;
    int mtx = m >> 5;
    int lm = m & 31;
    int rb = lm >> 4;
    int l16 = lm & 15;
    int rowbit = l16 >> 3;
    int lane = (l16 & 7) * 4 + (p & 3);
    int jj = ((p >> 2) & 1) * 2 + rowbit;
    return (uint32_t)(((((kt * 4 + mtx) * 2 + rb) * 32 + lane) * 4 + jj) * 4 + (j & 1) * 2);
}

// ray setup: normalize dir, AABB near/far
__device__ __forceinline__ void ray_setup(const float* __restrict__ rays_o,
                                          const float* __restrict__ rays_d, int ray,
                                          float* ox, float* oy, float* oz,
                                          float* dx, float* dy, float* dz,
                                          float* near_t, float* dtv) {
    float o0 = rays_o[ray*3+0], o1 = rays_o[ray*3+1], o2 = rays_o[ray*3+2];
    float rdx = rays_d[ray*3+0], rdy = rays_d[ray*3+1], rdz = rays_d[ray*3+2];
    float inv_norm = rsqrtf(rdx*rdx + rdy*rdy + rdz*rdz);
    float d0 = rdx*inv_norm, d1 = rdy*inv_norm, d2 = rdz*inv_norm;
    float dd;
    dd = (fabsf(d0) < 1e-8f) ? 1e-8f : d0; float i0 = __fdividef(1.0f, dd);
    dd = (fabsf(d1) < 1e-8f) ? 1e-8f : d1; float i1 = __fdividef(1.0f, dd);
    dd = (fabsf(d2) < 1e-8f) ? 1e-8f : d2; float i2 = __fdividef(1.0f, dd);
    float t0x=(-1.f-o0)*i0, t1x=(1.f-o0)*i0;
    float t0y=(-1.f-o1)*i1, t1y=(1.f-o1)*i1;
    float t0z=(-1.f-o2)*i2, t1z=(1.f-o2)*i2;
    float nx=fminf(t0x,t1x), fx=fmaxf(t0x,t1x);
    float ny=fminf(t0y,t1y), fy=fmaxf(t0y,t1y);
    float nz=fminf(t0z,t1z), fz=fmaxf(t0z,t1z);
    float nt = fmaxf(fmaxf(nx, fmaxf(ny, nz)), 0.02f);
    float ft = fminf(fmaxf(fx, fmaxf(fy, fz)), 1000.f);
    ft = fmaxf(ft, nt + 0.001f);
    *ox = o0; *oy = o1; *oz = o2; *dx = d0; *dy = d1; *dz = d2;
    *near_t = nt; *dtv = (ft - nt) * (1.0f/128.0f);
}

// posenc for one ray, executed by threads tid in [128, 1024)
__device__ __forceinline__ void posenc_phase(int tid, uint32_t sb, float* dirs,
                                             float ox, float oy, float oz,
                                             float dx, float dy, float dz,
                                             float near_t, float dtv) {
    const int m = tid & 127;
    const int gg = (tid >> 7) - 1;      // 0..6
    float t = near_t + ((float)m + 0.5f) * dtv;
    float px = ox + t*dx, py = oy + t*dy, pz = oz + t*dz;
    const uint32_t xbase = sb + SM_ACT + ACT_XF;
    if (gg < 6) {
        int ci = gg >> 1, half = gg & 1;
        float pv = (ci == 0) ? px : ((ci == 1) ? py : pz);
        float f = half ? 32.f : 1.f;
        #pragma unroll
        for (int q = 0; q < 5; q++) {
            int qq = half*5 + q;
            float s, c;
            sincos_fast(pv * f, &s, &c);
            sts_bf16(xbase + xf_addr(m, 3 + ci*10 + qq), s);
            sts_bf16(xbase + xf_addr(m, 33 + ci*10 + qq), c);
            f *= 2.f;
        }
    } else {
        sts_bf16(xbase + xf_addr(m, 0), px);
        sts_bf16(xbase + xf_addr(m, 1), py);
        sts_bf16(xbase + xf_addr(m, 2), pz);
        sts_bf16(xbase + xf_addr(m, 63), 0.f);
        if (m < 27) {
            int j = m;
            float dv[3] = {dx, dy, dz};
            float v;
            if (j < 3) v = dv[j];
            else if (j < 15) { int jj = j-3;  float s,c; sincos_fast(dv[jj>>2]*(float)(1<<(jj&3)), &s, &c); v = s; }
            else             { int jj = j-15; float s,c; sincos_fast(dv[jj>>2]*(float)(1<<(jj&3)), &s, &c); v = c; }
            dirs[j] = v;
        }
    }
}

// ===================== prep: pack weights, N-tile pairs per uint4 =====================
__global__ void prep_pack(const float* __restrict__ W1, const float* __restrict__ W2,
                          const float* __restrict__ W3) {
    int s = blockIdx.x * 256 + threadIdx.x;
    if (s >= 21504) return;
    int lane = s & 31;
    int qn = lane >> 2, qk = (lane & 3) * 2;
    const float* W; int kbase, n, ldn, kmax; uint32_t base, idx;
    if (s < 4096) {                       // P1: 4 kt x 32 nt
        int t = s >> 5;
        int kt = t >> 5, nt = t & 31;
        kbase = kt * 16; n = nt * 8 + qn; W = W1; ldn = 256; kmax = 63;
        base = 0; idx = (uint32_t)(((kt * 16 + (nt >> 1)) * 32 + lane) * 4 + (nt & 1) * 2);
    } else if (s < 20480) {               // P2: 16 kt x 32 nt
        int t = (s - 4096) >> 5;
        int kt = t >> 5, nt = t & 31;
        kbase = kt * 16; n = nt * 8 + qn; W = W2; ldn = 256; kmax = 256;
        base = 8192; idx = (uint32_t)(((kt * 16 + (nt >> 1)) * 32 + lane) * 4 + (nt & 1) * 2);
    } else {                              // P3: 16 kt x 2 nt
        int t = (s - 20480) >> 5;
        int kt = t >> 1, nt = t & 1;
        kbase = kt * 16; n = nt * 8 + qn; W = W3; ldn = 16; kmax = 256;
        base = 40960; idx = (uint32_t)((kt * 32 + lane) * 4 + nt * 2);
    }
    int k0 = kbase + qk;
    float e0 = (k0     < kmax) ? W[(k0)     * ldn + n] : 0.f;
    float e1 = (k0 + 1 < kmax) ? W[(k0 + 1) * ldn + n] : 0.f;
    float e2 = (k0 + 8 < kmax) ? W[(k0 + 8) * ldn + n] : 0.f;
    float e3 = (k0 + 9 < kmax) ? W[(k0 + 9) * ldn + n] : 0.f;
    g_pack[base + idx]     = bf16_pack2(e0, e1);
    g_pack[base + idx + 1] = bf16_pack2(e2, e3);
}

// ===================== main kernel: persistent, 148 CTAs x 1024 thr =====================
__global__ void __launch_bounds__(1024, 1)
nerf_mma(const float* __restrict__ rays_o, const float* __restrict__ rays_d,
         const float* __restrict__ b1, const float* __restrict__ b2,
         const float* __restrict__ b3,
         const float* __restrict__ Wc1, const float* __restrict__ bc1,
         const float* __restrict__ Wc2, const float* __restrict__ bc2,
         float* __restrict__ out)
{
    extern __shared__ char smem[];
    const int tid  = threadIdx.x;
    const int lane = tid & 31;
    const int w    = tid >> 5;
    const int mt   = w & 3;               // M-tile (32 rows)
    const int nq   = w >> 2;              // N-eighth (32 cols)
    const int la3  = lane & 3;
    const int qk   = la3 * 2;
    const int r0   = mt * 32 + (lane >> 2);

    const uint32_t sb = smem_u32(smem);
    float* b1s  = (float*)(smem + SM_B1);
    float* b2s  = (float*)(smem + SM_B2);
    float* b3s  = (float*)(smem + SM_B3);
    float* dirs = (float*)(smem + SM_DIR);
    float* comp = (float*)(smem + SM_COMP);
    float* bc2s = (float*)(smem + SM_BC2);
    float* dc   = (float*)(smem + SM_DIRC);
    float* geosf= (float*)(smem + SM_ACT + ACT_GEOS);
    float* acc3 = (float*)(smem + SM_ACT + ACT_ACC3);
    const uint4* P1q = (const uint4*)(smem + SM_ACT);
    const uint4* P2q = (const uint4*)(smem + SM_P2);
    const uint4* P3q = (const uint4*)(smem + SM_P3);
    const char* gp = (const char*)g_pack;

    // ---- resident staging (once per CTA): P2, P3, color weights ----
    {
        uint32_t d2 = sb + SM_P2, d3 = sb + SM_P3;
        #pragma unroll
        for (int j = 0; j < 8; j++)
            CP16(d2 + (uint32_t)(tid + j * 1024) * 16, gp + 32768 + (tid + j * 1024) * 16);
        if (tid < 512) CP16(d3 + (uint32_t)tid * 16, gp + 163840 + tid * 16);
        if (tid < 672) CP16(sb + SM_WC1 + (uint32_t)tid*16, (const char*)Wc1 + tid*16);
        if (tid < 48)  CP16(sb + SM_WC2 + (uint32_t)tid*16, (const char*)Wc2 + tid*16);
        if (tid < 16)  CP16(sb + SM_BC1 + (uint32_t)tid*16, (const char*)bc1 + tid*16);
        CP_COMMIT();
        // P1 for first ray
        CP16(sb + SM_ACT + (uint32_t)tid * 16,          gp + tid * 16);
        CP16(sb + SM_ACT + (uint32_t)(tid + 1024) * 16, gp + (tid + 1024) * 16);
        CP_COMMIT();
    }
    if (tid < 256) { b1s[tid] = b1[tid]; b2s[tid] = b2[tid]; }
    if (tid < 16) b3s[tid] = b3[tid];
    if (tid < 3)  bc2s[tid] = bc2[tid];

    // prologue posenc for first ray (warps 4-31)
    if (tid >= 128) {
        float ox, oy, oz, dx, dy, dz, near_t, dtv;
        ray_setup(rays_o, rays_d, blockIdx.x, &ox,&oy,&oz,&dx,&dy,&dz,&near_t,&dtv);
        posenc_phase(tid, sb, dirs, ox, oy, oz, dx, dy, dz, near_t, dtv);
    }
    CP_WAIT(0);
    __syncthreads();

    const int G = gridDim.x;
    for (int ray = blockIdx.x; ray < 4096; ray += G) {

        // ---------------- phase 1: Layer 1 MMAs ----------------
        float acc[2][4][4];
        #pragma unroll
        for (int rb = 0; rb < 2; rb++)
            #pragma unroll
            for (int ct = 0; ct < 4; ct++)
                #pragma unroll
                for (int j = 0; j < 4; j++) acc[rb][ct][j] = 0.f;
        {
            const uint4* pA = (const uint4*)(smem + SM_ACT + ACT_XF) + mt*64 + lane;
            #pragma unroll
            for (int kt = 0; kt < 4; kt++) {
                uint4 a0 = pA[kt*256];
                uint4 a1 = pA[kt*256 + 32];
                uint4 p0 = P1q[(kt*16 + nq*2)*32 + lane];
                uint4 p1 = P1q[(kt*16 + nq*2 + 1)*32 + lane];
                MMA(acc[0][0], a0.x, a0.y, a0.z, a0.w, p0.x, p0.y);
                MMA(acc[0][1], a0.x, a0.y, a0.z, a0.w, p0.z, p0.w);
                MMA(acc[0][2], a0.x, a0.y, a0.z, a0.w, p1.x, p1.y);
                MMA(acc[0][3], a0.x, a0.y, a0.z, a0.w, p1.z, p1.w);
                MMA(acc[1][0], a1.x, a1.y, a1.z, a1.w, p0.x, p0.y);
                MMA(acc[1][1], a1.x, a1.y, a1.z, a1.w, p0.z, p0.w);
                MMA(acc[1][2], a1.x, a1.y, a1.z, a1.w, p1.x, p1.y);
                MMA(acc[1][3], a1.x, a1.y, a1.z, a1.w, p1.z, p1.w);
            }
        }
        __syncthreads();               // [2] XF/P1 reads done

        // ---------------- phase 2: epilogue H1 -> A-fragment layout ----------------
        #pragma unroll
        for (int ct = 0; ct < 4; ct++) {
            int n0 = nq*32 + ct*8 + qk;
            float2 bb = *(const float2*)(b1s + n0);
            int kt = nq*2 + (ct >> 1);
            int j0 = (ct & 1) * 2;
            #pragma unroll
            for (int rb = 0; rb < 2; rb++) {
                uint32_t v0 = bf16_pack2(fmaxf(acc[rb][ct][0] + bb.x, 0.f), fmaxf(acc[rb][ct][1] + bb.y, 0.f));
                uint32_t v1 = bf16_pack2(fmaxf(acc[rb][ct][2] + bb.x, 0.f), fmaxf(acc[rb][ct][3] + bb.y, 0.f));
                uint32_t idx = (uint32_t)((((kt*4 + mt)*2 + rb)*32 + lane)*4 + j0);
                *(uint2*)(smem + SM_ACT + idx*4) = make_uint2(v0, v1);
            }
        }
        __syncthreads();               // [3]

        // ---------------- phase 3: Layer 2 MMAs (16 K-tiles) ----------------
        #pragma unroll
        for (int rb = 0; rb < 2; rb++)
            #pragma unroll
            for (int ct = 0; ct < 4; ct++)
                #pragma unroll
                for (int j = 0; j < 4; j++) acc[rb][ct][j] = 0.f;
        {
            const uint4* pA = (const uint4*)(smem + SM_ACT) + mt*64 + lane;
            #pragma unroll
            for (int kt = 0; kt < 16; kt++) {
                uint4 a0 = pA[kt*256];
                uint4 a1 = pA[kt*256 + 32];
                uint4 p0 = P2q[(kt*16 + nq*2)*32 + lane];
                uint4 p1 = P2q[(kt*16 + nq*2 + 1)*32 + lane];
                MMA(acc[0][0], a0.x, a0.y, a0.z, a0.w, p0.x, p0.y);
                MMA(acc[0][1], a0.x, a0.y, a0.z, a0.w, p0.z, p0.w);
                MMA(acc[0][2], a0.x, a0.y, a0.z, a0.w, p1.x, p1.y);
                MMA(acc[0][3], a0.x, a0.y, a0.z, a0.w, p1.z, p1.w);
                MMA(acc[1][0], a1.x, a1.y, a1.z, a1.w, p0.x, p0.y);
                MMA(acc[1][1], a1.x, a1.y, a1.z, a1.w, p0.z, p0.w);
                MMA(acc[1][2], a1.x, a1.y, a1.z, a1.w, p1.x, p1.y);
                MMA(acc[1][3], a1.x, a1.y, a1.z, a1.w, p1.z, p1.w);
            }
        }
        __syncthreads();               // [4] H1F reads done; ACT reusable

        // ---------------- phase 4: stage P1(next) + zero GEOS/ACC3 ----------------
        CP16(sb + SM_ACT + (uint32_t)tid * 16,          gp + tid * 16);
        CP16(sb + SM_ACT + (uint32_t)(tid + 1024) * 16, gp + (tid + 1024) * 16);
        CP_COMMIT();
        #pragma unroll
        for (int i = tid; i < ZERO_FLOATS; i += 1024)
            geosf[i] = 0.f;
        __syncthreads();               // [5]

        // ---------------- phase 5: Layer 3 MMAs + atomic reduce; dc ----------------
        {
            float geo[2][2][4];
            #pragma unroll
            for (int rb = 0; rb < 2; rb++)
                #pragma unroll
                for (int nt = 0; nt < 2; nt++)
                    #pragma unroll
                    for (int j = 0; j < 4; j++) geo[rb][nt][j] = 0.f;
            #pragma unroll
            for (int ii = 0; ii < 2; ii++) {
                int kt3 = nq*2 + ii;
                uint4 bq = P3q[kt3*32 + lane];
                int n0 = nq*32 + (2*ii)*8 + qk;
                float2 bb0 = *(const float2*)(b2s + n0);
                float2 bb1 = *(const float2*)(b2s + n0 + 8);
                #pragma unroll
                for (int rb = 0; rb < 2; rb++) {
                    uint32_t a0 = bf16_pack2(fmaxf(acc[rb][2*ii][0] + bb0.x, 0.f),  fmaxf(acc[rb][2*ii][1] + bb0.y, 0.f));
                    uint32_t a1 = bf16_pack2(fmaxf(acc[rb][2*ii][2] + bb0.x, 0.f),  fmaxf(acc[rb][2*ii][3] + bb0.y, 0.f));
                    uint32_t a2 = bf16_pack2(fmaxf(acc[rb][2*ii+1][0] + bb1.x, 0.f), fmaxf(acc[rb][2*ii+1][1] + bb1.y, 0.f));
                    uint32_t a3 = bf16_pack2(fmaxf(acc[rb][2*ii+1][2] + bb1.x, 0.f), fmaxf(acc[rb][2*ii+1][3] + bb1.y, 0.f));
                    MMA(geo[rb][0], a0, a1, a2, a3, bq.x, bq.y);
                    MMA(geo[rb][1], a0, a1, a2, a3, bq.z, bq.w);
                }
            }
            #pragma unroll
            for (int rb = 0; rb < 2; rb++)
                #pragma unroll
                for (int nt = 0; nt < 2; nt++) {
                    int c = nt*8 + qk;
                    int rr = r0 + rb*16;
                    atomicAdd(&geosf[c*132 + rr],       geo[rb][nt][0]);
                    atomicAdd(&geosf[(c+1)*132 + rr],   geo[rb][nt][1]);
                    atomicAdd(&geosf[c*132 + rr + 8],   geo[rb][nt][2]);
                    atomicAdd(&geosf[(c+1)*132 + rr+8], geo[rb][nt][3]);
                }
        }
        if (tid < 64) {   // dir contribution (ray-constant)
            int j = tid;
            const float* wc1s = (const float*)(smem + SM_WC1);
            const float* bc1s = (const float*)(smem + SM_BC1);
            float h = bc1s[j];
            #pragma unroll
            for (int i = 0; i < 27; i++)
                h = fmaf(dirs[i], wc1s[i*64 + j], h);
            dc[j] = h;
        }
        __syncthreads();               // [6]

        // ---------------- phase 6: color j-slices + atomic accumulate ----------------
        {
            const float* wc1s = (const float*)(smem + SM_WC1);
            const float* wc2s = (const float*)(smem + SM_WC2);
            const int m = tid & 127, g = tid >> 7;
            float fea[15];
            #pragma unroll
            for (int i = 0; i < 15; i++) fea[i] = geosf[(1+i)*132 + m] + b3s[1+i];
            float a0 = 0.f, a1 = 0.f, a2 = 0.f;
            const int j0 = g * 8;
            #pragma unroll
            for (int jj = 0; jj < 8; jj++) {
                int j = j0 + jj;
                float h = dc[j];
                #pragma unroll
                for (int i = 0; i < 15; i++)
                    h = fmaf(fea[i], wc1s[(27+i)*64 + j], h);
                h = fmaxf(h, 0.f);
                a0 = fmaf(h, wc2s[j*3+0], a0);
                a1 = fmaf(h, wc2s[j*3+1], a1);
                a2 = fmaf(h, wc2s[j*3+2], a2);
            }
            atomicAdd(&acc3[m*5+0], a0);
            atomicAdd(&acc3[m*5+1], a1);
            atomicAdd(&acc3[m*5+2], a2);
        }
        __syncthreads();               // [7]

        // ---------------- phase 7: split tail ----------------
        if (tid < 128) {
            // warps 0-3: finalize comp, then warp 0 composites
            float ox, oy, oz, dx, dy, dz, near_t, dtv;
            ray_setup(rays_o, rays_d, ray, &ox,&oy,&oz,&dx,&dy,&dz,&near_t,&dtv);
            int m = tid;
            float a0 = acc3[m*5+0] + bc2s[0];
            float a1 = acc3[m*5+1] + bc2s[1];
            float a2 = acc3[m*5+2] + bc2s[2];
            float sx = geosf[0*132 + m] + b3s[0];
            float sigma = (sx > 20.f) ? sx : log1pf(__expf(sx));
            float alpha = 1.f - __expf(-sigma * dtv);
            comp[m*4+0] = alpha;
            comp[m*4+1] = 1.f / (1.f + __expf(-a0));
            comp[m*4+2] = 1.f / (1.f + __expf(-a1));
            comp[m*4+3] = 1.f / (1.f + __expf(-a2));
            asm volatile("bar.sync 1, 128;" ::: "memory");
            if (tid < 32) {
                float av[4];
                #pragma unroll
                for (int j = 0; j < 4; j++) av[j] = comp[(lane*4 + j)*4 + 0];
                float q0 = 1.f - av[0] + 1e-10f;
                float q1 = 1.f - av[1] + 1e-10f;
                float q2 = 1.f - av[2] + 1e-10f;
                float q3 = 1.f - av[3] + 1e-10f;
                float inc = ((q0*q1)*(q2*q3));
                #pragma unroll
                for (int off = 1; off < 32; off <<= 1) {
                    float t = __shfl_up_sync(0xFFFFFFFF, inc, off);
                    if (lane >= off) inc *= t;
                }
                float T = __shfl_up_sync(0xFFFFFFFF, inc, 1);
                if (lane == 0) T = 1.f;
                float wsum = 0.f, dsum = 0.f, r = 0.f, g = 0.f, b = 0.f;
                #pragma unroll
                for (int j = 0; j < 4; j++) {
                    int mm = lane*4 + j;
                    float alpha2 = av[j];
                    float wgt = (T > 1e-4f) ? alpha2 * T : 0.f;
                    wsum += wgt;
                    float tsv = near_t + ((float)mm + 0.5f) * dtv;
                    dsum = fmaf(wgt, tsv, dsum);
                    r = fmaf(wgt, comp[mm*4+1], r);
                    g = fmaf(wgt, comp[mm*4+2], g);
                    b = fmaf(wgt, comp[mm*4+3], b);
                    T *= (1.f - alpha2 + 1e-10f);
                }
                #pragma unroll
                for (int off = 16; off > 0; off >>= 1) {
                    wsum += __shfl_xor_sync(0xFFFFFFFF, wsum, off);
                    dsum += __shfl_xor_sync(0xFFFFFFFF, dsum, off);
                    r    += __shfl_xor_sync(0xFFFFFFFF, r, off);
                    g    += __shfl_xor_sync(0xFFFFFFFF, g, off);
                    b    += __shfl_xor_sync(0xFFFFFFFF, b, off);
                }
                if (lane == 0) {
                    float bgw = 1.f - wsum;
                    out[ray*3+0] = r + bgw;
                    out[ray*3+1] = g + bgw;
                    out[ray*3+2] = b + bgw;
                    out[4096*3 + ray] = dsum;
                    out[4096*4 + ray] = fminf(fmaxf(wsum, 1e-12f), 1000.f);
                }
            }
        } else {
            // warps 4-31: next-ray setup + posenc (into dead H1F region)
            int rn = ray + G;
            if (rn < 4096) {
                float ox, oy, oz, dx, dy, dz, near_t, dtv;
                ray_setup(rays_o, rays_d, rn, &ox,&oy,&oz,&dx,&dy,&dz,&near_t,&dtv);
                posenc_phase(tid, sb, dirs, ox, oy, oz, dx, dy, dz, near_t, dtv);
            }
        }
        CP_WAIT(0);                    // P1(next) landed
        __syncthreads();               // [1] -> next iteration
    }
}

// ===================== launch =====================
extern "C" void kernel_launch(void* const* d_in, const int* in_sizes, int n_in,
                              void* d_out, int out_size) {
    const float* rays_o = (const float*)d_in[0];
    const float* rays_d = (const float*)d_in[1];
    const float* W1  = (const float*)d_in[2];
    const float* b1  = (const float*)d_in[3];
    const float* W2  = (const float*)d_in[4];
    const float* b2  = (const float*)d_in[5];
    const float* W3  = (const float*)d_in[6];
    const float* b3  = (const float*)d_in[7];
    const float* Wc1 = (const float*)d_in[8];
    const float* bc1 = (const float*)d_in[9];
    const float* Wc2 = (const float*)d_in[10];
    const float* bc2 = (const float*)d_in[11];
    float* out = (float*)d_out;

    prep_pack<<<84, 256>>>(W1, W2, W3);
    cudaFuncSetAttribute(nerf_mma, cudaFuncAttributeMaxDynamicSharedMemorySize, SMEM_BYTES);
    nerf_mma<<<148, 1024, SMEM_BYTES>>>(rays_o, rays_d, b1, b2, b3,
                                        Wc1, bc1, Wc2, bc2, out);
}

// round 14
// speedup vs baseline: 1.0297x; 1.0297x over previous
#include <cuda_runtime.h>
#include <cuda_bf16.h>
#include <math.h>
#include <stdint.h>

// ===================== asm helpers =====================
__device__ __forceinline__ uint32_t smem_u32(const void* p) {
    uint32_t a;
    asm("{ .reg .u64 t; cvta.to.shared.u64 t, %1; cvt.u32.u64 %0, t; }" : "=r"(a) : "l"(p));
    return a;
}
#define CP16(dst_u32, src_ptr) \
    asm volatile("cp.async.cg.shared.global [%0], [%1], 16;" :: "r"(dst_u32), "l"(src_ptr) : "memory")
#define CP_COMMIT() asm volatile("cp.async.commit_group;" ::: "memory")
#define CP_WAIT(n)  asm volatile("cp.async.wait_group %0;" :: "n"(n) : "memory")

#define MMA(d, a0, a1, a2, a3, b0, b1) \
    asm("mma.sync.aligned.m16n8k16.row.col.f32.bf16.bf16.f32 " \
        "{%0,%1,%2,%3}, {%4,%5,%6,%7}, {%8,%9}, {%0,%1,%2,%3};" \
        : "+f"((d)[0]), "+f"((d)[1]), "+f"((d)[2]), "+f"((d)[3]) \
        : "r"(a0), "r"(a1), "r"(a2), "r"(a3), "r"(b0), "r"(b1))

// ===================== smem layout (persistent) =====================
#define SM_P2    0          // 131072  W2 fragments (resident)
#define SM_P3    131072     // 8192    W3 fragments (resident)
#define SM_ACT   139264     // 65536   per-ray region (phases alias):
                            //  A: P1(0..32768) | XF(32768..49152)
                            //  B: H1F (0..65536)
                            //  C: GEOS(49152..57600) | ACC3(57600..60160) | XF_next | P1_next
#define SM_B1    204800     // 1024
#define SM_B2    205824     // 1024
#define SM_B3    206848     // 64
#define SM_DIR   206912     // 128
#define SM_COMP  207040     // 2112  comp transposed [4][132] fp32
#define SM_BC2   209152     // 16
#define SM_WC1   209168     // 10752 (resident)
#define SM_WC2   219920     // 768
#define SM_BC1   220688     // 256
#define SM_DIRC  220944     // 256   dircontrib[64]
#define SM_RSET  221200     // 896   ray setups [28][8] fp32
#define SMEM_BYTES 222096

#define ACT_XF    32768
#define ACT_GEOS  49152     // [16][132] fp32 transposed, 8448 B
#define ACT_ACC3  57600     // [128][5] fp32, 2560 B
#define ZERO_FLOATS 2752    // GEOS (2112) + ACC3 (640)

// packed weight image (bf16 fragment order, uint4-paired): P1 32KB | P2 128KB | P3 8KB
__device__ __align__(128) uint32_t g_pack[43008];

__device__ __forceinline__ uint32_t bf16_pack2(float x, float y) {
    __nv_bfloat16 hx = __float2bfloat16(x), hy = __float2bfloat16(y);
    return (uint32_t)__bfloat16_as_ushort(hx) | ((uint32_t)__bfloat16_as_ushort(hy) << 16);
}
__device__ __forceinline__ void sts_bf16(uint32_t addr, float v) {
    uint16_t u = __bfloat16_as_ushort(__float2bfloat16(v));
    asm volatile("st.shared.u16 [%0], %1;" :: "r"(addr), "h"(u));
}
__device__ __forceinline__ void sincos_fast(float phi, float* s, float* c) {
    float k = rintf(phi * 0.15915494309f);
    float r = fmaf(-k, 6.2831854820251465f, phi);
    r = fmaf(-k, -1.7484556000744263e-07f, r);
    *s = __sinf(r);
    *c = __cosf(r);
}

// byte address (relative) of feature j of sample m inside an A-fragment array
__device__ __forceinline__ uint32_t xf_addr(int m, int j) {
    int p = j >> 1;
    int kt = p >> 3;
    int mtx = m >> 5;
    int lm = m & 31;
    int rb = lm >> 4;
    int l16 = lm & 15;
    int rowbit = l16 >> 3;
    int lane = (l16 & 7) * 4 + (p & 3);
    int jj = ((p >> 2) & 1) * 2 + rowbit;
    return (uint32_t)(((((kt * 4 + mtx) * 2 + rb) * 32 + lane) * 4 + jj) * 4 + (j & 1) * 2);
}

// ray setup: normalize dir, AABB near/far
__device__ __forceinline__ void ray_setup(const float* __restrict__ rays_o,
                                          const float* __restrict__ rays_d, int ray,
                                          float* ox, float* oy, float* oz,
                                          float* dx, float* dy, float* dz,
                                          float* near_t, float* dtv) {
    float o0 = rays_o[ray*3+0], o1 = rays_o[ray*3+1], o2 = rays_o[ray*3+2];
    float rdx = rays_d[ray*3+0], rdy = rays_d[ray*3+1], rdz = rays_d[ray*3+2];
    float inv_norm = rsqrtf(rdx*rdx + rdy*rdy + rdz*rdz);
    float d0 = rdx*inv_norm, d1 = rdy*inv_norm, d2 = rdz*inv_norm;
    float dd;
    dd = (fabsf(d0) < 1e-8f) ? 1e-8f : d0; float i0 = __fdividef(1.0f, dd);
    dd = (fabsf(d1) < 1e-8f) ? 1e-8f : d1; float i1 = __fdividef(1.0f, dd);
    dd = (fabsf(d2) < 1e-8f) ? 1e-8f : d2; float i2 = __fdividef(1.0f, dd);
    float t0x=(-1.f-o0)*i0, t1x=(1.f-o0)*i0;
    float t0y=(-1.f-o1)*i1, t1y=(1.f-o1)*i1;
    float t0z=(-1.f-o2)*i2, t1z=(1.f-o2)*i2;
    float nx=fminf(t0x,t1x), fx=fmaxf(t0x,t1x);
    float ny=fminf(t0y,t1y), fy=fmaxf(t0y,t1y);
    float nz=fminf(t0z,t1z), fz=fmaxf(t0z,t1z);
    float nt = fmaxf(fmaxf(nx, fmaxf(ny, nz)), 0.02f);
    float ft = fminf(fmaxf(fx, fmaxf(fy, fz)), 1000.f);
    ft = fmaxf(ft, nt + 0.001f);
    *ox = o0; *oy = o1; *oz = o2; *dx = d0; *dy = d1; *dz = d2;
    *near_t = nt; *dtv = (ft - nt) * (1.0f/128.0f);
}

// posenc for one ray, executed by threads tid in [128, 1024); rs = setup[8]
__device__ __forceinline__ void posenc_phase(int tid, uint32_t sb, float* dirs,
                                             const float* rs) {
    const int m = tid & 127;
    const int gg = (tid >> 7) - 1;      // 0..6
    float ox = rs[0], oy = rs[1], oz = rs[2];
    float dx = rs[3], dy = rs[4], dz = rs[5];
    float near_t = rs[6], dtv = rs[7];
    float t = near_t + ((float)m + 0.5f) * dtv;
    float px = ox + t*dx, py = oy + t*dy, pz = oz + t*dz;
    const uint32_t xbase = sb + SM_ACT + ACT_XF;
    if (gg < 6) {
        int ci = gg >> 1, half = gg & 1;
        float pv = (ci == 0) ? px : ((ci == 1) ? py : pz);
        float f = half ? 32.f : 1.f;
        #pragma unroll
        for (int q = 0; q < 5; q++) {
            int qq = half*5 + q;
            float s, c;
            sincos_fast(pv * f, &s, &c);
            sts_bf16(xbase + xf_addr(m, 3 + ci*10 + qq), s);
            sts_bf16(xbase + xf_addr(m, 33 + ci*10 + qq), c);
            f *= 2.f;
        }
    } else {
        sts_bf16(xbase + xf_addr(m, 0), px);
        sts_bf16(xbase + xf_addr(m, 1), py);
        sts_bf16(xbase + xf_addr(m, 2), pz);
        sts_bf16(xbase + xf_addr(m, 63), 0.f);
        if (m < 27) {
            int j = m;
            float dv[3] = {dx, dy, dz};
            float v;
            if (j < 3) v = dv[j];
            else if (j < 15) { int jj = j-3;  float s,c; sincos_fast(dv[jj>>2]*(float)(1<<(jj&3)), &s, &c); v = s; }
            else             { int jj = j-15; float s,c; sincos_fast(dv[jj>>2]*(float)(1<<(jj&3)), &s, &c); v = c; }
            dirs[j] = v;
        }
    }
}

// ===================== prep: pack weights, N-tile pairs per uint4 =====================
__global__ void prep_pack(const float* __restrict__ W1, const float* __restrict__ W2,
                          const float* __restrict__ W3) {
    int s = blockIdx.x * 256 + threadIdx.x;
    if (s >= 21504) return;
    int lane = s & 31;
    int qn = lane >> 2, qk = (lane & 3) * 2;
    const float* W; int kbase, n, ldn, kmax; uint32_t base, idx;
    if (s < 4096) {                       // P1: 4 kt x 32 nt
        int t = s >> 5;
        int kt = t >> 5, nt = t & 31;
        kbase = kt * 16; n = nt * 8 + qn; W = W1; ldn = 256; kmax = 63;
        base = 0; idx = (uint32_t)(((kt * 16 + (nt >> 1)) * 32 + lane) * 4 + (nt & 1) * 2);
    } else if (s < 20480) {               // P2: 16 kt x 32 nt
        int t = (s - 4096) >> 5;
        int kt = t >> 5, nt = t & 31;
        kbase = kt * 16; n = nt * 8 + qn; W = W2; ldn = 256; kmax = 256;
        base = 8192; idx = (uint32_t)(((kt * 16 + (nt >> 1)) * 32 + lane) * 4 + (nt & 1) * 2);
    } else {                              // P3: 16 kt x 2 nt
        int t = (s - 20480) >> 5;
        int kt = t >> 1, nt = t & 1;
        kbase = kt * 16; n = nt * 8 + qn; W = W3; ldn = 16; kmax = 256;
        base = 40960; idx = (uint32_t)((kt * 32 + lane) * 4 + nt * 2);
    }
    int k0 = kbase + qk;
    float e0 = (k0     < kmax) ? W[(k0)     * ldn + n] : 0.f;
    float e1 = (k0 + 1 < kmax) ? W[(k0 + 1) * ldn + n] : 0.f;
    float e2 = (k0 + 8 < kmax) ? W[(k0 + 8) * ldn + n] : 0.f;
    float e3 = (k0 + 9 < kmax) ? W[(k0 + 9) * ldn + n] : 0.f;
    g_pack[base + idx]     = bf16_pack2(e0, e1);
    g_pack[base + idx + 1] = bf16_pack2(e2, e3);
}

// ===================== main kernel: persistent, 148 CTAs x 1024 thr =====================
__global__ void __launch_bounds__(1024, 1)
nerf_mma(const float* __restrict__ rays_o, const float* __restrict__ rays_d,
         const float* __restrict__ b1, const float* __restrict__ b2,
         const float* __restrict__ b3,
         const float* __restrict__ Wc1, const float* __restrict__ bc1,
         const float* __restrict__ Wc2, const float* __restrict__ bc2,
         float* __restrict__ out)
{
    extern __shared__ char smem[];
    const int tid  = threadIdx.x;
    const int lane = tid & 31;
    const int w    = tid >> 5;
    const int mt   = w & 3;               // M-tile (32 rows)
    const int nq   = w >> 2;              // N-eighth (32 cols)
    const int la3  = lane & 3;
    const int qk   = la3 * 2;
    const int r0   = mt * 32 + (lane >> 2);
    const int G    = gridDim.x;

    const uint32_t sb = smem_u32(smem);
    float* b1s  = (float*)(smem + SM_B1);
    float* b2s  = (float*)(smem + SM_B2);
    float* b3s  = (float*)(smem + SM_B3);
    float* dirs = (float*)(smem + SM_DIR);
    float* compT= (float*)(smem + SM_COMP);   // [4][132]
    float* bc2s = (float*)(smem + SM_BC2);
    float* dc   = (float*)(smem + SM_DIRC);
    float* rsets= (float*)(smem + SM_RSET);   // [28][8]
    float* geosf= (float*)(smem + SM_ACT + ACT_GEOS);
    float* acc3 = (float*)(smem + SM_ACT + ACT_ACC3);
    const uint4* P1q = (const uint4*)(smem + SM_ACT);
    const uint4* P2q = (const uint4*)(smem + SM_P2);
    const uint4* P3q = (const uint4*)(smem + SM_P3);
    const char* gp = (const char*)g_pack;

    // ---- resident staging (once per CTA): P2, P3, color weights, P1(first) ----
    {
        uint32_t d2 = sb + SM_P2, d3 = sb + SM_P3;
        #pragma unroll
        for (int j = 0; j < 8; j++)
            CP16(d2 + (uint32_t)(tid + j * 1024) * 16, gp + 32768 + (tid + j * 1024) * 16);
        if (tid < 512) CP16(d3 + (uint32_t)tid * 16, gp + 163840 + tid * 16);
        if (tid < 672) CP16(sb + SM_WC1 + (uint32_t)tid*16, (const char*)Wc1 + tid*16);
        if (tid < 48)  CP16(sb + SM_WC2 + (uint32_t)tid*16, (const char*)Wc2 + tid*16);
        if (tid < 16)  CP16(sb + SM_BC1 + (uint32_t)tid*16, (const char*)bc1 + tid*16);
        CP_COMMIT();
        CP16(sb + SM_ACT + (uint32_t)tid * 16,          gp + tid * 16);
        CP16(sb + SM_ACT + (uint32_t)(tid + 1024) * 16, gp + (tid + 1024) * 16);
        CP_COMMIT();
    }
    if (tid < 256) { b1s[tid] = b1[tid]; b2s[tid] = b2[tid]; }
    if (tid < 16) b3s[tid] = b3[tid];
    if (tid < 3)  bc2s[tid] = bc2[tid];

    // ---- per-CTA ray-setup cache (all rays this CTA will process) ----
    if (tid < 28) {
        int r = blockIdx.x + tid * G;
        if (r < 4096) {
            float ox, oy, oz, dx, dy, dz, nt, dt;
            ray_setup(rays_o, rays_d, r, &ox,&oy,&oz,&dx,&dy,&dz,&nt,&dt);
            float* rs = rsets + tid * 8;
            rs[0]=ox; rs[1]=oy; rs[2]=oz; rs[3]=dx; rs[4]=dy; rs[5]=dz; rs[6]=nt; rs[7]=dt;
        }
    }
    __syncthreads();

    // prologue posenc for first ray (warps 4-31)
    if (tid >= 128) posenc_phase(tid, sb, dirs, rsets);
    CP_WAIT(0);
    __syncthreads();

    int it = 0;
    for (int ray = blockIdx.x; ray < 4096; ray += G, it++) {

        // ---------------- phase 1: Layer 1 MMAs ----------------
        float acc[2][4][4];
        #pragma unroll
        for (int rb = 0; rb < 2; rb++)
            #pragma unroll
            for (int ct = 0; ct < 4; ct++)
                #pragma unroll
                for (int j = 0; j < 4; j++) acc[rb][ct][j] = 0.f;
        {
            const uint4* pA = (const uint4*)(smem + SM_ACT + ACT_XF) + mt*64 + lane;
            #pragma unroll
            for (int kt = 0; kt < 4; kt++) {
                uint4 a0 = pA[kt*256];
                uint4 a1 = pA[kt*256 + 32];
                uint4 p0 = P1q[(kt*16 + nq*2)*32 + lane];
                uint4 p1 = P1q[(kt*16 + nq*2 + 1)*32 + lane];
                MMA(acc[0][0], a0.x, a0.y, a0.z, a0.w, p0.x, p0.y);
                MMA(acc[0][1], a0.x, a0.y, a0.z, a0.w, p0.z, p0.w);
                MMA(acc[0][2], a0.x, a0.y, a0.z, a0.w, p1.x, p1.y);
                MMA(acc[0][3], a0.x, a0.y, a0.z, a0.w, p1.z, p1.w);
                MMA(acc[1][0], a1.x, a1.y, a1.z, a1.w, p0.x, p0.y);
                MMA(acc[1][1], a1.x, a1.y, a1.z, a1.w, p0.z, p0.w);
                MMA(acc[1][2], a1.x, a1.y, a1.z, a1.w, p1.x, p1.y);
                MMA(acc[1][3], a1.x, a1.y, a1.z, a1.w, p1.z, p1.w);
            }
        }
        __syncthreads();               // [2] XF/P1 reads done

        // ---------------- phase 2: epilogue H1 -> A-fragment layout ----------------
        #pragma unroll
        for (int ct = 0; ct < 4; ct++) {
            int n0 = nq*32 + ct*8 + qk;
            float2 bb = *(const float2*)(b1s + n0);
            int kt = nq*2 + (ct >> 1);
            int j0 = (ct & 1) * 2;
            #pragma unroll
            for (int rb = 0; rb < 2; rb++) {
                uint32_t v0 = bf16_pack2(fmaxf(acc[rb][ct][0] + bb.x, 0.f), fmaxf(acc[rb][ct][1] + bb.y, 0.f));
                uint32_t v1 = bf16_pack2(fmaxf(acc[rb][ct][2] + bb.x, 0.f), fmaxf(acc[rb][ct][3] + bb.y, 0.f));
                uint32_t idx = (uint32_t)((((kt*4 + mt)*2 + rb)*32 + lane)*4 + j0);
                *(uint2*)(smem + SM_ACT + idx*4) = make_uint2(v0, v1);
            }
        }
        __syncthreads();               // [3]

        // ---------------- phase 3: Layer 2 MMAs (16 K-tiles) ----------------
        #pragma unroll
        for (int rb = 0; rb < 2; rb++)
            #pragma unroll
            for (int ct = 0; ct < 4; ct++)
                #pragma unroll
                for (int j = 0; j < 4; j++) acc[rb][ct][j] = 0.f;
        {
            const uint4* pA = (const uint4*)(smem + SM_ACT) + mt*64 + lane;
            #pragma unroll
            for (int kt = 0; kt < 16; kt++) {
                uint4 a0 = pA[kt*256];
                uint4 a1 = pA[kt*256 + 32];
                uint4 p0 = P2q[(kt*16 + nq*2)*32 + lane];
                uint4 p1 = P2q[(kt*16 + nq*2 + 1)*32 + lane];
                MMA(acc[0][0], a0.x, a0.y, a0.z, a0.w, p0.x, p0.y);
                MMA(acc[0][1], a0.x, a0.y, a0.z, a0.w, p0.z, p0.w);
                MMA(acc[0][2], a0.x, a0.y, a0.z, a0.w, p1.x, p1.y);
                MMA(acc[0][3], a0.x, a0.y, a0.z, a0.w, p1.z, p1.w);
                MMA(acc[1][0], a1.x, a1.y, a1.z, a1.w, p0.x, p0.y);
                MMA(acc[1][1], a1.x, a1.y, a1.z, a1.w, p0.z, p0.w);
                MMA(acc[1][2], a1.x, a1.y, a1.z, a1.w, p1.x, p1.y);
                MMA(acc[1][3], a1.x, a1.y, a1.z, a1.w, p1.z, p1.w);
            }
        }
        __syncthreads();               // [4] H1F reads done; ACT reusable

        // ---------------- phase 4: stage P1(next) + zero GEOS/ACC3 ----------------
        CP16(sb + SM_ACT + (uint32_t)tid * 16,          gp + tid * 16);
        CP16(sb + SM_ACT + (uint32_t)(tid + 1024) * 16, gp + (tid + 1024) * 16);
        CP_COMMIT();
        #pragma unroll
        for (int i = tid; i < ZERO_FLOATS; i += 1024)
            geosf[i] = 0.f;
        __syncthreads();               // [5]

        // ---------------- phase 5: Layer 3 MMAs + atomic reduce; dc ----------------
        {
            float geo[2][2][4];
            #pragma unroll
            for (int rb = 0; rb < 2; rb++)
                #pragma unroll
                for (int nt = 0; nt < 2; nt++)
                    #pragma unroll
                    for (int j = 0; j < 4; j++) geo[rb][nt][j] = 0.f;
            #pragma unroll
            for (int ii = 0; ii < 2; ii++) {
                int kt3 = nq*2 + ii;
                uint4 bq = P3q[kt3*32 + lane];
                int n0 = nq*32 + (2*ii)*8 + qk;
                float2 bb0 = *(const float2*)(b2s + n0);
                float2 bb1 = *(const float2*)(b2s + n0 + 8);
                #pragma unroll
                for (int rb = 0; rb < 2; rb++) {
                    uint32_t a0 = bf16_pack2(fmaxf(acc[rb][2*ii][0] + bb0.x, 0.f),  fmaxf(acc[rb][2*ii][1] + bb0.y, 0.f));
                    uint32_t a1 = bf16_pack2(fmaxf(acc[rb][2*ii][2] + bb0.x, 0.f),  fmaxf(acc[rb][2*ii][3] + bb0.y, 0.f));
                    uint32_t a2 = bf16_pack2(fmaxf(acc[rb][2*ii+1][0] + bb1.x, 0.f), fmaxf(acc[rb][2*ii+1][1] + bb1.y, 0.f));
                    uint32_t a3 = bf16_pack2(fmaxf(acc[rb][2*ii+1][2] + bb1.x, 0.f), fmaxf(acc[rb][2*ii+1][3] + bb1.y, 0.f));
                    MMA(geo[rb][0], a0, a1, a2, a3, bq.x, bq.y);
                    MMA(geo[rb][1], a0, a1, a2, a3, bq.z, bq.w);
                }
            }
            #pragma unroll
            for (int rb = 0; rb < 2; rb++)
                #pragma unroll
                for (int nt = 0; nt < 2; nt++) {
                    int c = nt*8 + qk;
                    int rr = r0 + rb*16;
                    atomicAdd(&geosf[c*132 + rr],       geo[rb][nt][0]);
                    atomicAdd(&geosf[(c+1)*132 + rr],   geo[rb][nt][1]);
                    atomicAdd(&geosf[c*132 + rr + 8],   geo[rb][nt][2]);
                    atomicAdd(&geosf[(c+1)*132 + rr+8], geo[rb][nt][3]);
                }
        }
        if (tid < 64) {   // dir contribution (ray-constant)
            int j = tid;
            const float* wc1s = (const float*)(smem + SM_WC1);
            const float* bc1s = (const float*)(smem + SM_BC1);
            float h = bc1s[j];
            #pragma unroll
            for (int i = 0; i < 27; i++)
                h = fmaf(dirs[i], wc1s[i*64 + j], h);
            dc[j] = h;
        }
        __syncthreads();               // [6]

        // ---------------- phase 6: color j-slices + atomic accumulate ----------------
        {
            const float* wc1s = (const float*)(smem + SM_WC1);
            const float* wc2s = (const float*)(smem + SM_WC2);
            const int m = tid & 127, g = tid >> 7;
            float fea[15];
            #pragma unroll
            for (int i = 0; i < 15; i++) fea[i] = geosf[(1+i)*132 + m] + b3s[1+i];
            float a0 = 0.f, a1 = 0.f, a2 = 0.f;
            const int j0 = g * 8;
            #pragma unroll
            for (int jj = 0; jj < 8; jj++) {
                int j = j0 + jj;
                float h = dc[j];
                #pragma unroll
                for (int i = 0; i < 15; i++)
                    h = fmaf(fea[i], wc1s[(27+i)*64 + j], h);
                h = fmaxf(h, 0.f);
                a0 = fmaf(h, wc2s[j*3+0], a0);
                a1 = fmaf(h, wc2s[j*3+1], a1);
                a2 = fmaf(h, wc2s[j*3+2], a2);
            }
            atomicAdd(&acc3[m*5+0], a0);
            atomicAdd(&acc3[m*5+1], a1);
            atomicAdd(&acc3[m*5+2], a2);
        }
        __syncthreads();               // [7]

        // ---------------- phase 7: split tail ----------------
        if (tid < 128) {
            const float* rs = rsets + it*8;
            float near_t = rs[6], dtv = rs[7];
            int m = tid;
            float a0 = acc3[m*5+0] + bc2s[0];
            float a1 = acc3[m*5+1] + bc2s[1];
            float a2 = acc3[m*5+2] + bc2s[2];
            float sx = geosf[0*132 + m] + b3s[0];
            float sigma = (sx > 20.f) ? sx : log1pf(__expf(sx));
            float alpha = 1.f - __expf(-sigma * dtv);
            compT[0*132 + m] = alpha;
            compT[1*132 + m] = 1.f / (1.f + __expf(-a0));
            compT[2*132 + m] = 1.f / (1.f + __expf(-a1));
            compT[3*132 + m] = 1.f / (1.f + __expf(-a2));
            asm volatile("bar.sync 1, 128;" ::: "memory");
            if (tid < 32) {
                float4 av = *(const float4*)(compT + 0*132 + lane*4);
                float4 rv = *(const float4*)(compT + 1*132 + lane*4);
                float4 gv = *(const float4*)(compT + 2*132 + lane*4);
                float4 bv = *(const float4*)(compT + 3*132 + lane*4);
                float q0 = 1.f - av.x + 1e-10f;
                float q1 = 1.f - av.y + 1e-10f;
                float q2 = 1.f - av.z + 1e-10f;
                float q3 = 1.f - av.w + 1e-10f;
                float inc = ((q0*q1)*(q2*q3));
                #pragma unroll
                for (int off = 1; off < 32; off <<= 1) {
                    float t = __shfl_up_sync(0xFFFFFFFF, inc, off);
                    if (lane >= off) inc *= t;
                }
                float T = __shfl_up_sync(0xFFFFFFFF, inc, 1);
                if (lane == 0) T = 1.f;
                float alp[4] = {av.x, av.y, av.z, av.w};
                float rr[4] = {rv.x, rv.y, rv.z, rv.w};
                float gg[4] = {gv.x, gv.y, gv.z, gv.w};
                float bb[4] = {bv.x, bv.y, bv.z, bv.w};
                float wsum = 0.f, dsum = 0.f, r = 0.f, g = 0.f, b = 0.f;
                #pragma unroll
                for (int j = 0; j < 4; j++) {
                    int mm = lane*4 + j;
                    float wgt = (T > 1e-4f) ? alp[j] * T : 0.f;
                    wsum += wgt;
                    float tsv = near_t + ((float)mm + 0.5f) * dtv;
                    dsum = fmaf(wgt, tsv, dsum);
                    r = fmaf(wgt, rr[j], r);
                    g = fmaf(wgt, gg[j], g);
                    b = fmaf(wgt, bb[j], b);
                    T *= (1.f - alp[j] + 1e-10f);
                }
                #pragma unroll
                for (int off = 16; off > 0; off >>= 1) {
                    wsum += __shfl_xor_sync(0xFFFFFFFF, wsum, off);
                    dsum += __shfl_xor_sync(0xFFFFFFFF, dsum, off);
                    r    += __shfl_xor_sync(0xFFFFFFFF, r, off);
                    g    += __shfl_xor_sync(0xFFFFFFFF, g, off);
                    b    += __shfl_xor_sync(0xFFFFFFFF, b, off);
                }
                if (lane == 0) {
                    float bgw = 1.f - wsum;
                    out[ray*3+0] = r + bgw;
                    out[ray*3+1] = g + bgw;
                    out[ray*3+2] = b + bgw;
                    out[4096*3 + ray] = dsum;
                    out[4096*4 + ray] = fminf(fmaxf(wsum, 1e-12f), 1000.f);
                }
            }
        } else {
            // warps 4-31: next-ray posenc (into dead H1F region)
            if (ray + G < 4096)
                posenc_phase(tid, sb, dirs, rsets + (it+1)*8);
        }
        CP_WAIT(0);                    // P1(next) landed
        __syncthreads();               // [1] -> next iteration
    }
}

// ===================== launch =====================
extern "C" void kernel_launch(void* const* d_in, const int* in_sizes, int n_in,
                              void* d_out, int out_size) {
    const float* rays_o = (const float*)d_in[0];
    const float* rays_d = (const float*)d_in[1];
    const float* W1  = (const float*)d_in[2];
    const float* b1  = (const float*)d_in[3];
    const float* W2  = (const float*)d_in[4];
    const float* b2  = (const float*)d_in[5];
    const float* W3  = (const float*)d_in[6];
    const float* b3  = (const float*)d_in[7];
    const float* Wc1 = (const float*)d_in[8];
    const float* bc1 = (const float*)d_in[9];
    const float* Wc2 = (const float*)d_in[10];
    const float* bc2 = (const float*)d_in[11];
    float* out = (float*)d_out;

    prep_pack<<<84, 256>>>(W1, W2, W3);
    cudaFuncSetAttribute(nerf_mma, cudaFuncAttributeMaxDynamicSharedMemorySize, SMEM_BYTES);
    nerf_mma<<<148, 1024, SMEM_BYTES>>>(rays_o, rays_d, b1, b2, b3,
                                        Wc1, bc1, Wc2, bc2, out);
}

// round 15
// speedup vs baseline: 1.0574x; 1.0269x over previous
#include <cuda_runtime.h>
#include <cuda_bf16.h>
#include <math.h>
#include <stdint.h>

// ===================== asm helpers =====================
__device__ __forceinline__ uint32_t smem_u32(const void* p) {
    uint32_t a;
    asm("{ .reg .u64 t; cvta.to.shared.u64 t, %1; cvt.u32.u64 %0, t; }" : "=r"(a) : "l"(p));
    return a;
}
#define CP16(dst_u32, src_ptr) \
    asm volatile("cp.async.cg.shared.global [%0], [%1], 16;" :: "r"(dst_u32), "l"(src_ptr) : "memory")
#define CP_COMMIT() asm volatile("cp.async.commit_group;" ::: "memory")
#define CP_WAIT(n)  asm volatile("cp.async.wait_group %0;" :: "n"(n) : "memory")

#define MMA(d, a0, a1, a2, a3, b0, b1) \
    asm("mma.sync.aligned.m16n8k16.row.col.f32.bf16.bf16.f32 " \
        "{%0,%1,%2,%3}, {%4,%5,%6,%7}, {%8,%9}, {%0,%1,%2,%3};" \
        : "+f"((d)[0]), "+f"((d)[1]), "+f"((d)[2]), "+f"((d)[3]) \
        : "r"(a0), "r"(a1), "r"(a2), "r"(a3), "r"(b0), "r"(b1))

// X pair-layout stride (u32): 136 -> conflict-free posenc stores + A-frag loads
#define XS 136

// ===================== smem layout (persistent) =====================
#define SM_P2    0          // 131072  W2 fragments (resident)
#define SM_P3    131072     // 8192    W3 fragments (resident)
#define SM_ACT   139264     // 65536   per-ray region (phases alias):
                            //  A: P1(0..32768) | XF pairs [32][136]u32 (32768..50176)
                            //  B: H1F (0..65536)
                            //  C: GEOS(50176..58624) | ACC3(58624..61184) | XF_next | P1_next
#define SM_B1    204800     // 1024
#define SM_B2    205824     // 1024
#define SM_B3    206848     // 64
#define SM_DIR   206912     // 128
#define SM_COMP  207040     // 2112  comp transposed [4][132] fp32
#define SM_BC2   209152     // 16
#define SM_WC1   209168     // 10752 (resident)
#define SM_WC2   219920     // 768
#define SM_BC1   220688     // 256
#define SM_DIRC  220944     // 256   dircontrib[64]
#define SM_RSET  221200     // 896   ray setups [28][8] fp32
#define SMEM_BYTES 222096

#define ACT_XF    32768
#define ACT_GEOS  50176     // [16][132] fp32 transposed, 8448 B
#define ACT_ACC3  58624     // [128][5] fp32, 2560 B
#define ZERO_FLOATS 2752    // GEOS (2112) + ACC3 (640), contiguous from ACT_GEOS

// packed weight image (bf16 fragment order, uint4-paired): P1 32KB | P2 128KB | P3 8KB
__device__ __align__(128) uint32_t g_pack[43008];

__device__ __forceinline__ uint32_t bf16_pack2(float x, float y) {
    __nv_bfloat16 hx = __float2bfloat16(x), hy = __float2bfloat16(y);
    return (uint32_t)__bfloat16_as_ushort(hx) | ((uint32_t)__bfloat16_as_ushort(hy) << 16);
}
__device__ __forceinline__ void sts_bf16(uint32_t addr, float v) {
    uint16_t u = __bfloat16_as_ushort(__float2bfloat16(v));
    asm volatile("st.shared.u16 [%0], %1;" :: "r"(addr), "h"(u));
}
__device__ __forceinline__ void sincos_fast(float phi, float* s, float* c) {
    float k = rintf(phi * 0.15915494309f);
    float r = fmaf(-k, 6.2831854820251465f, phi);
    r = fmaf(-k, -1.7484556000744263e-07f, r);
    *s = __sinf(r);
    *c = __cosf(r);
}

// ray setup: normalize dir, AABB near/far
__device__ __forceinline__ void ray_setup(const float* __restrict__ rays_o,
                                          const float* __restrict__ rays_d, int ray,
                                          float* ox, float* oy, float* oz,
                                          float* dx, float* dy, float* dz,
                                          float* near_t, float* dtv) {
    float o0 = rays_o[ray*3+0], o1 = rays_o[ray*3+1], o2 = rays_o[ray*3+2];
    float rdx = rays_d[ray*3+0], rdy = rays_d[ray*3+1], rdz = rays_d[ray*3+2];
    float inv_norm = rsqrtf(rdx*rdx + rdy*rdy + rdz*rdz);
    float d0 = rdx*inv_norm, d1 = rdy*inv_norm, d2 = rdz*inv_norm;
    float dd;
    dd = (fabsf(d0) < 1e-8f) ? 1e-8f : d0; float i0 = __fdividef(1.0f, dd);
    dd = (fabsf(d1) < 1e-8f) ? 1e-8f : d1; float i1 = __fdividef(1.0f, dd);
    dd = (fabsf(d2) < 1e-8f) ? 1e-8f : d2; float i2 = __fdividef(1.0f, dd);
    float t0x=(-1.f-o0)*i0, t1x=(1.f-o0)*i0;
    float t0y=(-1.f-o1)*i1, t1y=(1.f-o1)*i1;
    float t0z=(-1.f-o2)*i2, t1z=(1.f-o2)*i2;
    float nx=fminf(t0x,t1x), fx=fmaxf(t0x,t1x);
    float ny=fminf(t0y,t1y), fy=fmaxf(t0y,t1y);
    float nz=fminf(t0z,t1z), fz=fmaxf(t0z,t1z);
    float nt = fmaxf(fmaxf(nx, fmaxf(ny, nz)), 0.02f);
    float ft = fminf(fmaxf(fx, fmaxf(fy, fz)), 1000.f);
    ft = fmaxf(ft, nt + 0.001f);
    *ox = o0; *oy = o1; *oz = o2; *dx = d0; *dy = d1; *dz = d2;
    *near_t = nt; *dtv = (ft - nt) * (1.0f/128.0f);
}

// posenc into XF pair layout [pair][XS] (conflict-free stores); tid in [128,1024)
__device__ __forceinline__ void posenc_phase(int tid, uint32_t sb, float* dirs,
                                             const float* rs) {
    const int m = tid & 127;
    const int gg = (tid >> 7) - 1;      // 0..6
    float ox = rs[0], oy = rs[1], oz = rs[2];
    float dx = rs[3], dy = rs[4], dz = rs[5];
    float near_t = rs[6], dtv = rs[7];
    float t = near_t + ((float)m + 0.5f) * dtv;
    float px = ox + t*dx, py = oy + t*dy, pz = oz + t*dz;
    const uint32_t xbase = sb + SM_ACT + ACT_XF;
    if (gg < 6) {
        int ci = gg >> 1, half = gg & 1;
        float pv = (ci == 0) ? px : ((ci == 1) ? py : pz);
        float f = half ? 32.f : 1.f;
        #pragma unroll
        for (int q = 0; q < 5; q++) {
            int qq = half*5 + q;
            float s, c;
            sincos_fast(pv * f, &s, &c);
            int j1 = 3 + ci*10 + qq, j2 = 33 + ci*10 + qq;
            sts_bf16(xbase + (uint32_t)(((j1 >> 1)*XS + m)*4 + (j1 & 1)*2), s);
            sts_bf16(xbase + (uint32_t)(((j2 >> 1)*XS + m)*4 + (j2 & 1)*2), c);
            f *= 2.f;
        }
    } else {
        *(uint32_t*)(xbase - sb + (uint32_t)(0*XS + m)*4 + (char*)0 + 0) = 0;  // placeholder (replaced below)
    }
    if (gg == 6) {
        // pair 0 = (px, py); pair 1 lo = pz; pair 31 hi = pad 0
        asm volatile("st.shared.b32 [%0], %1;" :: "r"(xbase + (uint32_t)((0*XS + m)*4)),
                     "r"(bf16_pack2(px, py)) : "memory");
        sts_bf16(xbase + (uint32_t)((1*XS + m)*4), pz);
        sts_bf16(xbase + (uint32_t)((31*XS + m)*4 + 2), 0.f);
        if (m < 27) {
            int j = m;
            float dv[3] = {dx, dy, dz};
            float v;
            if (j < 3) v = dv[j];
            else if (j < 15) { int jj = j-3;  float s,c; sincos_fast(dv[jj>>2]*(float)(1<<(jj&3)), &s, &c); v = s; }
            else             { int jj = j-15; float s,c; sincos_fast(dv[jj>>2]*(float)(1<<(jj&3)), &s, &c); v = c; }
            dirs[j] = v;
        }
    }
}

// ===================== prep: pack weights, N-tile pairs per uint4 =====================
__global__ void prep_pack(const float* __restrict__ W1, const float* __restrict__ W2,
                          const float* __restrict__ W3) {
    int s = blockIdx.x * 256 + threadIdx.x;
    if (s >= 21504) return;
    int lane = s & 31;
    int qn = lane >> 2, qk = (lane & 3) * 2;
    const float* W; int kbase, n, ldn, kmax; uint32_t base, idx;
    if (s < 4096) {                       // P1: 4 kt x 32 nt
        int t = s >> 5;
        int kt = t >> 5, nt = t & 31;
        kbase = kt * 16; n = nt * 8 + qn; W = W1; ldn = 256; kmax = 63;
        base = 0; idx = (uint32_t)(((kt * 16 + (nt >> 1)) * 32 + lane) * 4 + (nt & 1) * 2);
    } else if (s < 20480) {               // P2: 16 kt x 32 nt
        int t = (s - 4096) >> 5;
        int kt = t >> 5, nt = t & 31;
        kbase = kt * 16; n = nt * 8 + qn; W = W2; ldn = 256; kmax = 256;
        base = 8192; idx = (uint32_t)(((kt * 16 + (nt >> 1)) * 32 + lane) * 4 + (nt & 1) * 2);
    } else {                              // P3: 16 kt x 2 nt
        int t = (s - 20480) >> 5;
        int kt = t >> 1, nt = t & 1;
        kbase = kt * 16; n = nt * 8 + qn; W = W3; ldn = 16; kmax = 256;
        base = 40960; idx = (uint32_t)((kt * 32 + lane) * 4 + nt * 2);
    }
    int k0 = kbase + qk;
    float e0 = (k0     < kmax) ? W[(k0)     * ldn + n] : 0.f;
    float e1 = (k0 + 1 < kmax) ? W[(k0 + 1) * ldn + n] : 0.f;
    float e2 = (k0 + 8 < kmax) ? W[(k0 + 8) * ldn + n] : 0.f;
    float e3 = (k0 + 9 < kmax) ? W[(k0 + 9) * ldn + n] : 0.f;
    g_pack[base + idx]     = bf16_pack2(e0, e1);
    g_pack[base + idx + 1] = bf16_pack2(e2, e3);
}

// ===================== main kernel: persistent, 148 CTAs x 1024 thr =====================
__global__ void __launch_bounds__(1024, 1)
nerf_mma(const float* __restrict__ rays_o, const float* __restrict__ rays_d,
         const float* __restrict__ b1, const float* __restrict__ b2,
         const float* __restrict__ b3,
         const float* __restrict__ Wc1, const float* __restrict__ bc1,
         const float* __restrict__ Wc2, const float* __restrict__ bc2,
         float* __restrict__ out)
{
    extern __shared__ char smem[];
    const int tid  = threadIdx.x;
    const int lane = tid & 31;
    const int w    = tid >> 5;
    const int mt   = w & 3;               // M-tile (32 rows)
    const int nq   = w >> 2;              // N-eighth (32 cols)
    const int la3  = lane & 3;
    const int qk   = la3 * 2;
    const int r0   = mt * 32 + (lane >> 2);
    const int G    = gridDim.x;

    const uint32_t sb = smem_u32(smem);
    float* b1s  = (float*)(smem + SM_B1);
    float* b2s  = (float*)(smem + SM_B2);
    float* b3s  = (float*)(smem + SM_B3);
    float* dirs = (float*)(smem + SM_DIR);
    float* compT= (float*)(smem + SM_COMP);   // [4][132]
    float* bc2s = (float*)(smem + SM_BC2);
    float* dc   = (float*)(smem + SM_DIRC);
    float* rsets= (float*)(smem + SM_RSET);   // [28][8]
    float* geosf= (float*)(smem + SM_ACT + ACT_GEOS);
    float* acc3 = (float*)(smem + SM_ACT + ACT_ACC3);
    const uint32_t* Xu = (const uint32_t*)(smem + SM_ACT + ACT_XF);
    const uint4* P1q = (const uint4*)(smem + SM_ACT);
    const uint4* P2q = (const uint4*)(smem + SM_P2);
    const uint4* P3q = (const uint4*)(smem + SM_P3);
    const char* gp = (const char*)g_pack;

    // ---- resident staging (once per CTA): P2, P3, color weights, P1(first) ----
    {
        uint32_t d2 = sb + SM_P2, d3 = sb + SM_P3;
        #pragma unroll
        for (int j = 0; j < 8; j++)
            CP16(d2 + (uint32_t)(tid + j * 1024) * 16, gp + 32768 + (tid + j * 1024) * 16);
        if (tid < 512) CP16(d3 + (uint32_t)tid * 16, gp + 163840 + tid * 16);
        if (tid < 672) CP16(sb + SM_WC1 + (uint32_t)tid*16, (const char*)Wc1 + tid*16);
        if (tid < 48)  CP16(sb + SM_WC2 + (uint32_t)tid*16, (const char*)Wc2 + tid*16);
        if (tid < 16)  CP16(sb + SM_BC1 + (uint32_t)tid*16, (const char*)bc1 + tid*16);
        CP_COMMIT();
        CP16(sb + SM_ACT + (uint32_t)tid * 16,          gp + tid * 16);
        CP16(sb + SM_ACT + (uint32_t)(tid + 1024) * 16, gp + (tid + 1024) * 16);
        CP_COMMIT();
    }
    if (tid < 256) { b1s[tid] = b1[tid]; b2s[tid] = b2[tid]; }
    if (tid < 16) b3s[tid] = b3[tid];
    if (tid < 3)  bc2s[tid] = bc2[tid];

    // ---- per-CTA ray-setup cache ----
    if (tid < 28) {
        int r = blockIdx.x + tid * G;
        if (r < 4096) {
            float ox, oy, oz, dx, dy, dz, nt, dt;
            ray_setup(rays_o, rays_d, r, &ox,&oy,&oz,&dx,&dy,&dz,&nt,&dt);
            float* rs = rsets + tid * 8;
            rs[0]=ox; rs[1]=oy; rs[2]=oz; rs[3]=dx; rs[4]=dy; rs[5]=dz; rs[6]=nt; rs[7]=dt;
        }
    }
    __syncthreads();

    // prologue posenc for first ray (warps 4-31)
    if (tid >= 128) posenc_phase(tid, sb, dirs, rsets);
    CP_WAIT(0);
    __syncthreads();

    int it = 0;
    for (int ray = blockIdx.x; ray < 4096; ray += G, it++) {

        // ---------------- phase 1: Layer 1 MMAs (A from pair layout) ----------------
        float acc[2][4][4];
        #pragma unroll
        for (int rb = 0; rb < 2; rb++)
            #pragma unroll
            for (int ct = 0; ct < 4; ct++)
                #pragma unroll
                for (int j = 0; j < 4; j++) acc[rb][ct][j] = 0.f;
        #pragma unroll
        for (int kt = 0; kt < 4; kt++) {
            int pb0 = kt*8 + la3;
            uint32_t af[2][4];
            #pragma unroll
            for (int rb = 0; rb < 2; rb++) {
                int rr = r0 + rb*16;
                af[rb][0] = Xu[pb0*XS + rr];
                af[rb][1] = Xu[pb0*XS + rr + 8];
                af[rb][2] = Xu[(pb0+4)*XS + rr];
                af[rb][3] = Xu[(pb0+4)*XS + rr + 8];
            }
            uint4 p0 = P1q[(kt*16 + nq*2)*32 + lane];
            uint4 p1 = P1q[(kt*16 + nq*2 + 1)*32 + lane];
            #pragma unroll
            for (int rb = 0; rb < 2; rb++) {
                MMA(acc[rb][0], af[rb][0], af[rb][1], af[rb][2], af[rb][3], p0.x, p0.y);
                MMA(acc[rb][1], af[rb][0], af[rb][1], af[rb][2], af[rb][3], p0.z, p0.w);
                MMA(acc[rb][2], af[rb][0], af[rb][1], af[rb][2], af[rb][3], p1.x, p1.y);
                MMA(acc[rb][3], af[rb][0], af[rb][1], af[rb][2], af[rb][3], p1.z, p1.w);
            }
        }
        __syncthreads();               // [2] XF/P1 reads done

        // ---------------- phase 2: epilogue H1 -> A-fragment layout ----------------
        #pragma unroll
        for (int ct = 0; ct < 4; ct++) {
            int n0 = nq*32 + ct*8 + qk;
            float2 bb = *(const float2*)(b1s + n0);
            int kt = nq*2 + (ct >> 1);
            int j0 = (ct & 1) * 2;
            #pragma unroll
            for (int rb = 0; rb < 2; rb++) {
                uint32_t v0 = bf16_pack2(fmaxf(acc[rb][ct][0] + bb.x, 0.f), fmaxf(acc[rb][ct][1] + bb.y, 0.f));
                uint32_t v1 = bf16_pack2(fmaxf(acc[rb][ct][2] + bb.x, 0.f), fmaxf(acc[rb][ct][3] + bb.y, 0.f));
                uint32_t idx = (uint32_t)((((kt*4 + mt)*2 + rb)*32 + lane)*4 + j0);
                *(uint2*)(smem + SM_ACT + idx*4) = make_uint2(v0, v1);
            }
        }
        __syncthreads();               // [3]

        // ---------------- phase 3: Layer 2 MMAs (16 K-tiles) ----------------
        #pragma unroll
        for (int rb = 0; rb < 2; rb++)
            #pragma unroll
            for (int ct = 0; ct < 4; ct++)
                #pragma unroll
                for (int j = 0; j < 4; j++) acc[rb][ct][j] = 0.f;
        {
            const uint4* pA = (const uint4*)(smem + SM_ACT) + mt*64 + lane;
            #pragma unroll
            for (int kt = 0; kt < 16; kt++) {
                uint4 a0 = pA[kt*256];
                uint4 a1 = pA[kt*256 + 32];
                uint4 p0 = P2q[(kt*16 + nq*2)*32 + lane];
                uint4 p1 = P2q[(kt*16 + nq*2 + 1)*32 + lane];
                MMA(acc[0][0], a0.x, a0.y, a0.z, a0.w, p0.x, p0.y);
                MMA(acc[0][1], a0.x, a0.y, a0.z, a0.w, p0.z, p0.w);
                MMA(acc[0][2], a0.x, a0.y, a0.z, a0.w, p1.x, p1.y);
                MMA(acc[0][3], a0.x, a0.y, a0.z, a0.w, p1.z, p1.w);
                MMA(acc[1][0], a1.x, a1.y, a1.z, a1.w, p0.x, p0.y);
                MMA(acc[1][1], a1.x, a1.y, a1.z, a1.w, p0.z, p0.w);
                MMA(acc[1][2], a1.x, a1.y, a1.z, a1.w, p1.x, p1.y);
                MMA(acc[1][3], a1.x, a1.y, a1.z, a1.w, p1.z, p1.w);
            }
        }
        __syncthreads();               // [4] H1F reads done; ACT reusable

        // ---------------- phase 4: stage P1(next) + zero GEOS/ACC3 ----------------
        CP16(sb + SM_ACT + (uint32_t)tid * 16,          gp + tid * 16);
        CP16(sb + SM_ACT + (uint32_t)(tid + 1024) * 16, gp + (tid + 1024) * 16);
        CP_COMMIT();
        #pragma unroll
        for (int i = tid; i < ZERO_FLOATS; i += 1024)
            geosf[i] = 0.f;
        __syncthreads();               // [5]

        // ---------------- phase 5: Layer 3 MMAs + atomic reduce; dc ----------------
        {
            float geo[2][2][4];
            #pragma unroll
            for (int rb = 0; rb < 2; rb++)
                #pragma unroll
                for (int nt = 0; nt < 2; nt++)
                    #pragma unroll
                    for (int j = 0; j < 4; j++) geo[rb][nt][j] = 0.f;
            #pragma unroll
            for (int ii = 0; ii < 2; ii++) {
                int kt3 = nq*2 + ii;
                uint4 bq = P3q[kt3*32 + lane];
                int n0 = nq*32 + (2*ii)*8 + qk;
                float2 bb0 = *(const float2*)(b2s + n0);
                float2 bb1 = *(const float2*)(b2s + n0 + 8);
                #pragma unroll
                for (int rb = 0; rb < 2; rb++) {
                    uint32_t a0 = bf16_pack2(fmaxf(acc[rb][2*ii][0] + bb0.x, 0.f),  fmaxf(acc[rb][2*ii][1] + bb0.y, 0.f));
                    uint32_t a1 = bf16_pack2(fmaxf(acc[rb][2*ii][2] + bb0.x, 0.f),  fmaxf(acc[rb][2*ii][3] + bb0.y, 0.f));
                    uint32_t a2 = bf16_pack2(fmaxf(acc[rb][2*ii+1][0] + bb1.x, 0.f), fmaxf(acc[rb][2*ii+1][1] + bb1.y, 0.f));
                    uint32_t a3 = bf16_pack2(fmaxf(acc[rb][2*ii+1][2] + bb1.x, 0.f), fmaxf(acc[rb][2*ii+1][3] + bb1.y, 0.f));
                    MMA(geo[rb][0], a0, a1, a2, a3, bq.x, bq.y);
                    MMA(geo[rb][1], a0, a1, a2, a3, bq.z, bq.w);
                }
            }
            #pragma unroll
            for (int rb = 0; rb < 2; rb++)
                #pragma unroll
                for (int nt = 0; nt < 2; nt++) {
                    int c = nt*8 + qk;
                    int rr = r0 + rb*16;
                    atomicAdd(&geosf[c*132 + rr],       geo[rb][nt][0]);
                    atomicAdd(&geosf[(c+1)*132 + rr],   geo[rb][nt][1]);
                    atomicAdd(&geosf[c*132 + rr + 8],   geo[rb][nt][2]);
                    atomicAdd(&geosf[(c+1)*132 + rr+8], geo[rb][nt][3]);
                }
        }
        if (tid < 64) {   // dir contribution (ray-constant)
            int j = tid;
            const float* wc1s = (const float*)(smem + SM_WC1);
            const float* bc1s = (const float*)(smem + SM_BC1);
            float h = bc1s[j];
            #pragma unroll
            for (int i = 0; i < 27; i++)
                h = fmaf(dirs[i], wc1s[i*64 + j], h);
            dc[j] = h;
        }
        __syncthreads();               // [6]

        // ---------------- phase 6: color j-slices + atomic accumulate ----------------
        {
            const float* wc1s = (const float*)(smem + SM_WC1);
            const float* wc2s = (const float*)(smem + SM_WC2);
            const int m = tid & 127, g = tid >> 7;
            float fea[15];
            #pragma unroll
            for (int i = 0; i < 15; i++) fea[i] = geosf[(1+i)*132 + m] + b3s[1+i];
            float a0 = 0.f, a1 = 0.f, a2 = 0.f;
            const int j0 = g * 8;
            #pragma unroll
            for (int jj = 0; jj < 8; jj++) {
                int j = j0 + jj;
                float h = dc[j];
                #pragma unroll
                for (int i = 0; i < 15; i++)
                    h = fmaf(fea[i], wc1s[(27+i)*64 + j], h);
                h = fmaxf(h, 0.f);
                a0 = fmaf(h, wc2s[j*3+0], a0);
                a1 = fmaf(h, wc2s[j*3+1], a1);
                a2 = fmaf(h, wc2s[j*3+2], a2);
            }
            atomicAdd(&acc3[m*5+0], a0);
            atomicAdd(&acc3[m*5+1], a1);
            atomicAdd(&acc3[m*5+2], a2);
        }
        __syncthreads();               // [7]

        // ---------------- phase 7: split tail ----------------
        if (tid < 128) {
            const float* rs = rsets + it*8;
            float near_t = rs[6], dtv = rs[7];
            int m = tid;
            float a0 = acc3[m*5+0] + bc2s[0];
            float a1 = acc3[m*5+1] + bc2s[1];
            float a2 = acc3[m*5+2] + bc2s[2];
            float sx = geosf[0*132 + m] + b3s[0];
            float sigma = (sx > 20.f) ? sx : log1pf(__expf(sx));
            float alpha = 1.f - __expf(-sigma * dtv);
            compT[0*132 + m] = alpha;
            compT[1*132 + m] = 1.f / (1.f + __expf(-a0));
            compT[2*132 + m] = 1.f / (1.f + __expf(-a1));
            compT[3*132 + m] = 1.f / (1.f + __expf(-a2));
            asm volatile("bar.sync 1, 128;" ::: "memory");
            if (tid < 32) {
                float4 av = *(const float4*)(compT + 0*132 + lane*4);
                float4 rv = *(const float4*)(compT + 1*132 + lane*4);
                float4 gv = *(const float4*)(compT + 2*132 + lane*4);
                float4 bv = *(const float4*)(compT + 3*132 + lane*4);
                float q0 = 1.f - av.x + 1e-10f;
                float q1 = 1.f - av.y + 1e-10f;
                float q2 = 1.f - av.z + 1e-10f;
                float q3 = 1.f - av.w + 1e-10f;
                float inc = ((q0*q1)*(q2*q3));
                #pragma unroll
                for (int off = 1; off < 32; off <<= 1) {
                    float t = __shfl_up_sync(0xFFFFFFFF, inc, off);
                    if (lane >= off) inc *= t;
                }
                float T = __shfl_up_sync(0xFFFFFFFF, inc, 1);
                if (lane == 0) T = 1.f;
                float alp[4] = {av.x, av.y, av.z, av.w};
                float rr[4] = {rv.x, rv.y, rv.z, rv.w};
                float gg[4] = {gv.x, gv.y, gv.z, gv.w};
                float bb[4] = {bv.x, bv.y, bv.z, bv.w};
                float wsum = 0.f, dsum = 0.f, r = 0.f, g = 0.f, b = 0.f;
                #pragma unroll
                for (int j = 0; j < 4; j++) {
                    int mm = lane*4 + j;
                    float wgt = (T > 1e-4f) ? alp[j] * T : 0.f;
                    wsum += wgt;
                    float tsv = near_t + ((float)mm + 0.5f) * dtv;
                    dsum = fmaf(wgt, tsv, dsum);
                    r = fmaf(wgt, rr[j], r);
                    g = fmaf(wgt, gg[j], g);
                    b = fmaf(wgt, bb[j], b);
                    T *= (1.f - alp[j] + 1e-10f);
                }
                #pragma unroll
                for (int off = 16; off > 0; off >>= 1) {
                    wsum += __shfl_xor_sync(0xFFFFFFFF, wsum, off);
                    dsum += __shfl_xor_sync(0xFFFFFFFF, dsum, off);
                    r    += __shfl_xor_sync(0xFFFFFFFF, r, off);
                    g    += __shfl_xor_sync(0xFFFFFFFF, g, off);
                    b    += __shfl_xor_sync(0xFFFFFFFF, b, off);
                }
                if (lane == 0) {
                    float bgw = 1.f - wsum;
                    out[ray*3+0] = r + bgw;
                    out[ray*3+1] = g + bgw;
                    out[ray*3+2] = b + bgw;
                    out[4096*3 + ray] = dsum;
                    out[4096*4 + ray] = fminf(fmaxf(wsum, 1e-12f), 1000.f);
                }
            }
        } else {
            // warps 4-31: next-ray posenc (into dead region)
            if (ray + G < 4096)
                posenc_phase(tid, sb, dirs, rsets + (it+1)*8);
        }
        CP_WAIT(0);                    // P1(next) landed
        __syncthreads();               // [1] -> next iteration
    }
}

// ===================== launch =====================
extern "C" void kernel_launch(void* const* d_in, const int* in_sizes, int n_in,
                              void* d_out, int out_size) {
    const float* rays_o = (const float*)d_in[0];
    const float* rays_d = (const float*)d_in[1];
    const float* W1  = (const float*)d_in[2];
    const float* b1  = (const float*)d_in[3];
    const float* W2  = (const float*)d_in[4];
    const float* b2  = (const float*)d_in[5];
    const float* W3  = (const float*)d_in[6];
    const float* b3  = (const float*)d_in[7];
    const float* Wc1 = (const float*)d_in[8];
    const float* bc1 = (const float*)d_in[9];
    const float* Wc2 = (const float*)d_in[10];
    const float* bc2 = (const float*)d_in[11];
    float* out = (float*)d_out;

    prep_pack<<<84, 256>>>(W1, W2, W3);
    cudaFuncSetAttribute(nerf_mma, cudaFuncAttributeMaxDynamicSharedMemorySize, SMEM_BYTES);
    nerf_mma<<<148, 1024, SMEM_BYTES>>>(rays_o, rays_d, b1, b2, b3,
                                        Wc1, bc1, Wc2, bc2, out);
}

// round 16
// speedup vs baseline: 1.0727x; 1.0145x over previous
#include <cuda_runtime.h>
#include <cuda_bf16.h>
#include <math.h>
#include <stdint.h>

// ===================== asm helpers =====================
__device__ __forceinline__ uint32_t smem_u32(const void* p) {
    uint32_t a;
    asm("{ .reg .u64 t; cvta.to.shared.u64 t, %1; cvt.u32.u64 %0, t; }" : "=r"(a) : "l"(p));
    return a;
}
#define CP16(dst_u32, src_ptr) \
    asm volatile("cp.async.cg.shared.global [%0], [%1], 16;" :: "r"(dst_u32), "l"(src_ptr) : "memory")
#define CP_COMMIT() asm volatile("cp.async.commit_group;" ::: "memory")
#define CP_WAIT(n)  asm volatile("cp.async.wait_group %0;" :: "n"(n) : "memory")

#define MMA(d, a0, a1, a2, a3, b0, b1) \
    asm("mma.sync.aligned.m16n8k16.row.col.f32.bf16.bf16.f32 " \
        "{%0,%1,%2,%3}, {%4,%5,%6,%7}, {%8,%9}, {%0,%1,%2,%3};" \
        : "+f"((d)[0]), "+f"((d)[1]), "+f"((d)[2]), "+f"((d)[3]) \
        : "r"(a0), "r"(a1), "r"(a2), "r"(a3), "r"(b0), "r"(b1))

// X pair-layout stride (u32): 136 -> conflict-free posenc stores + A-frag loads
#define XS 136

// ===================== smem layout (persistent) =====================
#define SM_P2    0          // 131072  W2 fragments (resident)
#define SM_P3    131072     // 8192    W3 fragments (resident)
#define SM_ACT   139264     // 65536   per-ray region:
                            //  A: P1(0..32768) | XF pairs [32][136]u32 (32768..50176)
                            //  B: H1F (0..65536)
#define SM_B1    204800     // 1024
#define SM_B2    205824     // 1024
#define SM_B3    206848     // 64
#define SM_DIR   206912     // 128
#define SM_BC2   207040     // 16
#define SM_WC1   207056     // 10752 (resident)
#define SM_WC2   217808     // 768
#define SM_BC1   218576     // 256
#define SM_DIRC  218832     // 256   dircontrib[64]
#define SM_RSET  219088     // 896   ray setups [28][8] fp32
#define SM_GEOS  219984     // 8448  [16][132] fp32 transposed (outside ACT!)
#define SM_ACCR  228432     // 512
#define SM_ACCG  228944     // 512
#define SM_ACCB  229456     // 512
#define SM_COMP  229968     // 2112  comp transposed [4][132] fp32
#define SMEM_BYTES 232080

#define ACT_XF    32768
#define ZERO_FLOATS 2496    // GEOS (2112) + ACCR/G/B (384), contiguous from SM_GEOS

// packed weight image (bf16 fragment order, uint4-paired): P1 32KB | P2 128KB | P3 8KB
__device__ __align__(128) uint32_t g_pack[43008];

__device__ __forceinline__ uint32_t bf16_pack2(float x, float y) {
    __nv_bfloat16 hx = __float2bfloat16(x), hy = __float2bfloat16(y);
    return (uint32_t)__bfloat16_as_ushort(hx) | ((uint32_t)__bfloat16_as_ushort(hy) << 16);
}
__device__ __forceinline__ void sts_bf16(uint32_t addr, float v) {
    uint16_t u = __bfloat16_as_ushort(__float2bfloat16(v));
    asm volatile("st.shared.u16 [%0], %1;" :: "r"(addr), "h"(u));
}
__device__ __forceinline__ void sincos_fast(float phi, float* s, float* c) {
    float k = rintf(phi * 0.15915494309f);
    float r = fmaf(-k, 6.2831854820251465f, phi);
    r = fmaf(-k, -1.7484556000744263e-07f, r);
    *s = __sinf(r);
    *c = __cosf(r);
}

// ray setup: normalize dir, AABB near/far
__device__ __forceinline__ void ray_setup(const float* __restrict__ rays_o,
                                          const float* __restrict__ rays_d, int ray,
                                          float* ox, float* oy, float* oz,
                                          float* dx, float* dy, float* dz,
                                          float* near_t, float* dtv) {
    float o0 = rays_o[ray*3+0], o1 = rays_o[ray*3+1], o2 = rays_o[ray*3+2];
    float rdx = rays_d[ray*3+0], rdy = rays_d[ray*3+1], rdz = rays_d[ray*3+2];
    float inv_norm = rsqrtf(rdx*rdx + rdy*rdy + rdz*rdz);
    float d0 = rdx*inv_norm, d1 = rdy*inv_norm, d2 = rdz*inv_norm;
    float dd;
    dd = (fabsf(d0) < 1e-8f) ? 1e-8f : d0; float i0 = __fdividef(1.0f, dd);
    dd = (fabsf(d1) < 1e-8f) ? 1e-8f : d1; float i1 = __fdividef(1.0f, dd);
    dd = (fabsf(d2) < 1e-8f) ? 1e-8f : d2; float i2 = __fdividef(1.0f, dd);
    float t0x=(-1.f-o0)*i0, t1x=(1.f-o0)*i0;
    float t0y=(-1.f-o1)*i1, t1y=(1.f-o1)*i1;
    float t0z=(-1.f-o2)*i2, t1z=(1.f-o2)*i2;
    float nx=fminf(t0x,t1x), fx=fmaxf(t0x,t1x);
    float ny=fminf(t0y,t1y), fy=fmaxf(t0y,t1y);
    float nz=fminf(t0z,t1z), fz=fmaxf(t0z,t1z);
    float nt = fmaxf(fmaxf(nx, fmaxf(ny, nz)), 0.02f);
    float ft = fminf(fmaxf(fx, fmaxf(fy, fz)), 1000.f);
    ft = fmaxf(ft, nt + 0.001f);
    *ox = o0; *oy = o1; *oz = o2; *dx = d0; *dy = d1; *dz = d2;
    *near_t = nt; *dtv = (ft - nt) * (1.0f/128.0f);
}

// posenc into XF pair layout [pair][XS] (conflict-free stores); tid in [128,1024)
__device__ __forceinline__ void posenc_phase(int tid, uint32_t sb, float* dirs,
                                             const float* rs) {
    const int m = tid & 127;
    const int gg = (tid >> 7) - 1;      // 0..6
    float ox = rs[0], oy = rs[1], oz = rs[2];
    float dx = rs[3], dy = rs[4], dz = rs[5];
    float near_t = rs[6], dtv = rs[7];
    float t = near_t + ((float)m + 0.5f) * dtv;
    float px = ox + t*dx, py = oy + t*dy, pz = oz + t*dz;
    const uint32_t xbase = sb + SM_ACT + ACT_XF;
    if (gg < 6) {
        int ci = gg >> 1, half = gg & 1;
        float pv = (ci == 0) ? px : ((ci == 1) ? py : pz);
        float f = half ? 32.f : 1.f;
        #pragma unroll
        for (int q = 0; q < 5; q++) {
            int qq = half*5 + q;
            float s, c;
            sincos_fast(pv * f, &s, &c);
            int j1 = 3 + ci*10 + qq, j2 = 33 + ci*10 + qq;
            sts_bf16(xbase + (uint32_t)(((j1 >> 1)*XS + m)*4 + (j1 & 1)*2), s);
            sts_bf16(xbase + (uint32_t)(((j2 >> 1)*XS + m)*4 + (j2 & 1)*2), c);
            f *= 2.f;
        }
    } else {
        // pair 0 = (px, py); pair 1 lo = pz; pair 31 hi = pad 0
        asm volatile("st.shared.b32 [%0], %1;" :: "r"(xbase + (uint32_t)((0*XS + m)*4)),
                     "r"(bf16_pack2(px, py)) : "memory");
        sts_bf16(xbase + (uint32_t)((1*XS + m)*4), pz);
        sts_bf16(xbase + (uint32_t)((31*XS + m)*4 + 2), 0.f);
        if (m < 27) {
            int j = m;
            float dv[3] = {dx, dy, dz};
            float v;
            if (j < 3) v = dv[j];
            else if (j < 15) { int jj = j-3;  float s,c; sincos_fast(dv[jj>>2]*(float)(1<<(jj&3)), &s, &c); v = s; }
            else             { int jj = j-15; float s,c; sincos_fast(dv[jj>>2]*(float)(1<<(jj&3)), &s, &c); v = c; }
            dirs[j] = v;
        }
    }
}

// ===================== prep: pack weights, N-tile pairs per uint4 =====================
__global__ void prep_pack(const float* __restrict__ W1, const float* __restrict__ W2,
                          const float* __restrict__ W3) {
    int s = blockIdx.x * 256 + threadIdx.x;
    if (s >= 21504) return;
    int lane = s & 31;
    int qn = lane >> 2, qk = (lane & 3) * 2;
    const float* W; int kbase, n, ldn, kmax; uint32_t base, idx;
    if (s < 4096) {                       // P1: 4 kt x 32 nt
        int t = s >> 5;
        int kt = t >> 5, nt = t & 31;
        kbase = kt * 16; n = nt * 8 + qn; W = W1; ldn = 256; kmax = 63;
        base = 0; idx = (uint32_t)(((kt * 16 + (nt >> 1)) * 32 + lane) * 4 + (nt & 1) * 2);
    } else if (s < 20480) {               // P2: 16 kt x 32 nt
        int t = (s - 4096) >> 5;
        int kt = t >> 5, nt = t & 31;
        kbase = kt * 16; n = nt * 8 + qn; W = W2; ldn = 256; kmax = 256;
        base = 8192; idx = (uint32_t)(((kt * 16 + (nt >> 1)) * 32 + lane) * 4 + (nt & 1) * 2);
    } else {                              // P3: 16 kt x 2 nt
        int t = (s - 20480) >> 5;
        int kt = t >> 1, nt = t & 1;
        kbase = kt * 16; n = nt * 8 + qn; W = W3; ldn = 16; kmax = 256;
        base = 40960; idx = (uint32_t)((kt * 32 + lane) * 4 + nt * 2);
    }
    int k0 = kbase + qk;
    float e0 = (k0     < kmax) ? W[(k0)     * ldn + n] : 0.f;
    float e1 = (k0 + 1 < kmax) ? W[(k0 + 1) * ldn + n] : 0.f;
    float e2 = (k0 + 8 < kmax) ? W[(k0 + 8) * ldn + n] : 0.f;
    float e3 = (k0 + 9 < kmax) ? W[(k0 + 9) * ldn + n] : 0.f;
    g_pack[base + idx]     = bf16_pack2(e0, e1);
    g_pack[base + idx + 1] = bf16_pack2(e2, e3);
}

// ===================== main kernel: persistent, 148 CTAs x 1024 thr =====================
__global__ void __launch_bounds__(1024, 1)
nerf_mma(const float* __restrict__ rays_o, const float* __restrict__ rays_d,
         const float* __restrict__ b1, const float* __restrict__ b2,
         const float* __restrict__ b3,
         const float* __restrict__ Wc1, const float* __restrict__ bc1,
         const float* __restrict__ Wc2, const float* __restrict__ bc2,
         float* __restrict__ out)
{
    extern __shared__ char smem[];
    const int tid  = threadIdx.x;
    const int lane = tid & 31;
    const int w    = tid >> 5;
    const int mt   = w & 3;               // M-tile (32 rows)
    const int nq   = w >> 2;              // N-eighth (32 cols)
    const int la3  = lane & 3;
    const int qk   = la3 * 2;
    const int r0   = mt * 32 + (lane >> 2);
    const int G    = gridDim.x;

    const uint32_t sb = smem_u32(smem);
    float* b1s  = (float*)(smem + SM_B1);
    float* b2s  = (float*)(smem + SM_B2);
    float* b3s  = (float*)(smem + SM_B3);
    float* dirs = (float*)(smem + SM_DIR);
    float* compT= (float*)(smem + SM_COMP);   // [4][132]
    float* bc2s = (float*)(smem + SM_BC2);
    float* dc   = (float*)(smem + SM_DIRC);
    float* rsets= (float*)(smem + SM_RSET);   // [28][8]
    float* geosf= (float*)(smem + SM_GEOS);   // [16][132]
    float* accR = (float*)(smem + SM_ACCR);
    float* accG = (float*)(smem + SM_ACCG);
    float* accB = (float*)(smem + SM_ACCB);
    const uint32_t* Xu = (const uint32_t*)(smem + SM_ACT + ACT_XF);
    const uint4* P1q = (const uint4*)(smem + SM_ACT);
    const uint4* P2q = (const uint4*)(smem + SM_P2);
    const uint4* P3q = (const uint4*)(smem + SM_P3);
    const char* gp = (const char*)g_pack;

    // ---- resident staging (once per CTA): P2, P3, color weights, P1(first) ----
    {
        uint32_t d2 = sb + SM_P2, d3 = sb + SM_P3;
        #pragma unroll
        for (int j = 0; j < 8; j++)
            CP16(d2 + (uint32_t)(tid + j * 1024) * 16, gp + 32768 + (tid + j * 1024) * 16);
        if (tid < 512) CP16(d3 + (uint32_t)tid * 16, gp + 163840 + tid * 16);
        if (tid < 672) CP16(sb + SM_WC1 + (uint32_t)tid*16, (const char*)Wc1 + tid*16);
        if (tid < 48)  CP16(sb + SM_WC2 + (uint32_t)tid*16, (const char*)Wc2 + tid*16);
        if (tid < 16)  CP16(sb + SM_BC1 + (uint32_t)tid*16, (const char*)bc1 + tid*16);
        CP_COMMIT();
        CP16(sb + SM_ACT + (uint32_t)tid * 16,          gp + tid * 16);
        CP16(sb + SM_ACT + (uint32_t)(tid + 1024) * 16, gp + (tid + 1024) * 16);
        CP_COMMIT();
    }
    if (tid < 256) { b1s[tid] = b1[tid]; b2s[tid] = b2[tid]; }
    if (tid < 16) b3s[tid] = b3[tid];
    if (tid < 3)  bc2s[tid] = bc2[tid];

    // ---- per-CTA ray-setup cache ----
    if (tid < 28) {
        int r = blockIdx.x + tid * G;
        if (r < 4096) {
            float ox, oy, oz, dx, dy, dz, nt, dt;
            ray_setup(rays_o, rays_d, r, &ox,&oy,&oz,&dx,&dy,&dz,&nt,&dt);
            float* rs = rsets + tid * 8;
            rs[0]=ox; rs[1]=oy; rs[2]=oz; rs[3]=dx; rs[4]=dy; rs[5]=dz; rs[6]=nt; rs[7]=dt;
        }
    }
    __syncthreads();

    // prologue posenc for first ray (warps 4-31)
    if (tid >= 128) posenc_phase(tid, sb, dirs, rsets);
    CP_WAIT(0);
    __syncthreads();

    int it = 0;
    for (int ray = blockIdx.x; ray < 4096; ray += G, it++) {

        // ---------------- phase 1: Layer 1 MMAs + zero GEOS/ACC (hidden) --------
        #pragma unroll
        for (int i = tid; i < ZERO_FLOATS; i += 1024)
            geosf[i] = 0.f;

        float acc[2][4][4];
        #pragma unroll
        for (int rb = 0; rb < 2; rb++)
            #pragma unroll
            for (int ct = 0; ct < 4; ct++)
                #pragma unroll
                for (int j = 0; j < 4; j++) acc[rb][ct][j] = 0.f;
        #pragma unroll
        for (int kt = 0; kt < 4; kt++) {
            int pb0 = kt*8 + la3;
            uint32_t af[2][4];
            #pragma unroll
            for (int rb = 0; rb < 2; rb++) {
                int rr = r0 + rb*16;
                af[rb][0] = Xu[pb0*XS + rr];
                af[rb][1] = Xu[pb0*XS + rr + 8];
                af[rb][2] = Xu[(pb0+4)*XS + rr];
                af[rb][3] = Xu[(pb0+4)*XS + rr + 8];
            }
            uint4 p0 = P1q[(kt*16 + nq*2)*32 + lane];
            uint4 p1 = P1q[(kt*16 + nq*2 + 1)*32 + lane];
            #pragma unroll
            for (int rb = 0; rb < 2; rb++) {
                MMA(acc[rb][0], af[rb][0], af[rb][1], af[rb][2], af[rb][3], p0.x, p0.y);
                MMA(acc[rb][1], af[rb][0], af[rb][1], af[rb][2], af[rb][3], p0.z, p0.w);
                MMA(acc[rb][2], af[rb][0], af[rb][1], af[rb][2], af[rb][3], p1.x, p1.y);
                MMA(acc[rb][3], af[rb][0], af[rb][1], af[rb][2], af[rb][3], p1.z, p1.w);
            }
        }
        __syncthreads();               // [2] XF/P1 reads done

        // ---------------- phase 2: epilogue H1 -> A-fragment layout ----------------
        #pragma unroll
        for (int ct = 0; ct < 4; ct++) {
            int n0 = nq*32 + ct*8 + qk;
            float2 bb = *(const float2*)(b1s + n0);
            int kt = nq*2 + (ct >> 1);
            int j0 = (ct & 1) * 2;
            #pragma unroll
            for (int rb = 0; rb < 2; rb++) {
                uint32_t v0 = bf16_pack2(fmaxf(acc[rb][ct][0] + bb.x, 0.f), fmaxf(acc[rb][ct][1] + bb.y, 0.f));
                uint32_t v1 = bf16_pack2(fmaxf(acc[rb][ct][2] + bb.x, 0.f), fmaxf(acc[rb][ct][3] + bb.y, 0.f));
                uint32_t idx = (uint32_t)((((kt*4 + mt)*2 + rb)*32 + lane)*4 + j0);
                *(uint2*)(smem + SM_ACT + idx*4) = make_uint2(v0, v1);
            }
        }
        __syncthreads();               // [3]

        // ---------------- phase 3: Layer 2 MMAs (16 K-tiles) ----------------
        #pragma unroll
        for (int rb = 0; rb < 2; rb++)
            #pragma unroll
            for (int ct = 0; ct < 4; ct++)
                #pragma unroll
                for (int j = 0; j < 4; j++) acc[rb][ct][j] = 0.f;
        {
            const uint4* pA = (const uint4*)(smem + SM_ACT) + mt*64 + lane;
            #pragma unroll
            for (int kt = 0; kt < 16; kt++) {
                uint4 a0 = pA[kt*256];
                uint4 a1 = pA[kt*256 + 32];
                uint4 p0 = P2q[(kt*16 + nq*2)*32 + lane];
                uint4 p1 = P2q[(kt*16 + nq*2 + 1)*32 + lane];
                MMA(acc[0][0], a0.x, a0.y, a0.z, a0.w, p0.x, p0.y);
                MMA(acc[0][1], a0.x, a0.y, a0.z, a0.w, p0.z, p0.w);
                MMA(acc[0][2], a0.x, a0.y, a0.z, a0.w, p1.x, p1.y);
                MMA(acc[0][3], a0.x, a0.y, a0.z, a0.w, p1.z, p1.w);
                MMA(acc[1][0], a1.x, a1.y, a1.z, a1.w, p0.x, p0.y);
                MMA(acc[1][1], a1.x, a1.y, a1.z, a1.w, p0.z, p0.w);
                MMA(acc[1][2], a1.x, a1.y, a1.z, a1.w, p1.x, p1.y);
                MMA(acc[1][3], a1.x, a1.y, a1.z, a1.w, p1.z, p1.w);
            }
        }
        __syncthreads();               // [4] H1F reads done; ACT reusable

        // ---------------- phase 5: P1(next) stage + Layer 3 MMAs + reduce; dc ------
        CP16(sb + SM_ACT + (uint32_t)tid * 16,          gp + tid * 16);
        CP16(sb + SM_ACT + (uint32_t)(tid + 1024) * 16, gp + (tid + 1024) * 16);
        CP_COMMIT();
        {
            float geo[2][2][4];
            #pragma unroll
            for (int rb = 0; rb < 2; rb++)
                #pragma unroll
                for (int nt = 0; nt < 2; nt++)
                    #pragma unroll
                    for (int j = 0; j < 4; j++) geo[rb][nt][j] = 0.f;
            #pragma unroll
            for (int ii = 0; ii < 2; ii++) {
                int kt3 = nq*2 + ii;
                uint4 bq = P3q[kt3*32 + lane];
                int n0 = nq*32 + (2*ii)*8 + qk;
                float2 bb0 = *(const float2*)(b2s + n0);
                float2 bb1 = *(const float2*)(b2s + n0 + 8);
                #pragma unroll
                for (int rb = 0; rb < 2; rb++) {
                    uint32_t a0 = bf16_pack2(fmaxf(acc[rb][2*ii][0] + bb0.x, 0.f),  fmaxf(acc[rb][2*ii][1] + bb0.y, 0.f));
                    uint32_t a1 = bf16_pack2(fmaxf(acc[rb][2*ii][2] + bb0.x, 0.f),  fmaxf(acc[rb][2*ii][3] + bb0.y, 0.f));
                    uint32_t a2 = bf16_pack2(fmaxf(acc[rb][2*ii+1][0] + bb1.x, 0.f), fmaxf(acc[rb][2*ii+1][1] + bb1.y, 0.f));
                    uint32_t a3 = bf16_pack2(fmaxf(acc[rb][2*ii+1][2] + bb1.x, 0.f), fmaxf(acc[rb][2*ii+1][3] + bb1.y, 0.f));
                    MMA(geo[rb][0], a0, a1, a2, a3, bq.x, bq.y);
                    MMA(geo[rb][1], a0, a1, a2, a3, bq.z, bq.w);
                }
            }
            #pragma unroll
            for (int rb = 0; rb < 2; rb++)
                #pragma unroll
                for (int nt = 0; nt < 2; nt++) {
                    int c = nt*8 + qk;
                    int rr = r0 + rb*16;
                    atomicAdd(&geosf[c*132 + rr],       geo[rb][nt][0]);
                    atomicAdd(&geosf[(c+1)*132 + rr],   geo[rb][nt][1]);
                    atomicAdd(&geosf[c*132 + rr + 8],   geo[rb][nt][2]);
                    atomicAdd(&geosf[(c+1)*132 + rr+8], geo[rb][nt][3]);
                }
        }
        if (tid < 64) {   // dir contribution (ray-constant)
            int j = tid;
            const float* wc1s = (const float*)(smem + SM_WC1);
            const float* bc1s = (const float*)(smem + SM_BC1);
            float h = bc1s[j];
            #pragma unroll
            for (int i = 0; i < 27; i++)
                h = fmaf(dirs[i], wc1s[i*64 + j], h);
            dc[j] = h;
        }
        __syncthreads();               // [6]

        // ---------------- phase 6: color j-slices + atomic accumulate ----------------
        {
            const float* wc1s = (const float*)(smem + SM_WC1);
            const float* wc2s = (const float*)(smem + SM_WC2);
            const int m = tid & 127, g = tid >> 7;
            float fea[15];
            #pragma unroll
            for (int i = 0; i < 15; i++) fea[i] = geosf[(1+i)*132 + m] + b3s[1+i];
            float a0 = 0.f, a1 = 0.f, a2 = 0.f;
            const int j0 = g * 8;
            #pragma unroll
            for (int jj = 0; jj < 8; jj++) {
                int j = j0 + jj;
                float h = dc[j];
                #pragma unroll
                for (int i = 0; i < 15; i++)
                    h = fmaf(fea[i], wc1s[(27+i)*64 + j], h);
                h = fmaxf(h, 0.f);
                a0 = fmaf(h, wc2s[j*3+0], a0);
                a1 = fmaf(h, wc2s[j*3+1], a1);
                a2 = fmaf(h, wc2s[j*3+2], a2);
            }
            atomicAdd(&accR[m], a0);
            atomicAdd(&accG[m], a1);
            atomicAdd(&accB[m], a2);
        }
        __syncthreads();               // [7]

        // ---------------- phase 7: split tail ----------------
        if (tid < 128) {
            const float* rs = rsets + it*8;
            float near_t = rs[6], dtv = rs[7];
            int m = tid;
            float a0 = accR[m] + bc2s[0];
            float a1 = accG[m] + bc2s[1];
            float a2 = accB[m] + bc2s[2];
            float sx = geosf[0*132 + m] + b3s[0];
            float sigma = (sx > 20.f) ? sx : log1pf(__expf(sx));
            float alpha = 1.f - __expf(-sigma * dtv);
            compT[0*132 + m] = alpha;
            compT[1*132 + m] = 1.f / (1.f + __expf(-a0));
            compT[2*132 + m] = 1.f / (1.f + __expf(-a1));
            compT[3*132 + m] = 1.f / (1.f + __expf(-a2));
            asm volatile("bar.sync 1, 128;" ::: "memory");
            if (tid < 32) {
                float4 av = *(const float4*)(compT + 0*132 + lane*4);
                float4 rv = *(const float4*)(compT + 1*132 + lane*4);
                float4 gv = *(const float4*)(compT + 2*132 + lane*4);
                float4 bv = *(const float4*)(compT + 3*132 + lane*4);
                float q0 = 1.f - av.x + 1e-10f;
                float q1 = 1.f - av.y + 1e-10f;
                float q2 = 1.f - av.z + 1e-10f;
                float q3 = 1.f - av.w + 1e-10f;
                float inc = ((q0*q1)*(q2*q3));
                #pragma unroll
                for (int off = 1; off < 32; off <<= 1) {
                    float t = __shfl_up_sync(0xFFFFFFFF, inc, off);
                    if (lane >= off) inc *= t;
                }
                float T = __shfl_up_sync(0xFFFFFFFF, inc, 1);
                if (lane == 0) T = 1.f;
                float alp[4] = {av.x, av.y, av.z, av.w};
                float rr[4] = {rv.x, rv.y, rv.z, rv.w};
                float gg[4] = {gv.x, gv.y, gv.z, gv.w};
                float bb[4] = {bv.x, bv.y, bv.z, bv.w};
                float wsum = 0.f, dsum = 0.f, r = 0.f, g = 0.f, b = 0.f;
                #pragma unroll
                for (int j = 0; j < 4; j++) {
                    int mm = lane*4 + j;
                    float wgt = (T > 1e-4f) ? alp[j] * T : 0.f;
                    wsum += wgt;
                    float tsv = near_t + ((float)mm + 0.5f) * dtv;
                    dsum = fmaf(wgt, tsv, dsum);
                    r = fmaf(wgt, rr[j], r);
                    g = fmaf(wgt, gg[j], g);
                    b = fmaf(wgt, bb[j], b);
                    T *= (1.f - alp[j] + 1e-10f);
                }
                #pragma unroll
                for (int off = 16; off > 0; off >>= 1) {
                    wsum += __shfl_xor_sync(0xFFFFFFFF, wsum, off);
                    dsum += __shfl_xor_sync(0xFFFFFFFF, dsum, off);
                    r    += __shfl_xor_sync(0xFFFFFFFF, r, off);
                    g    += __shfl_xor_sync(0xFFFFFFFF, g, off);
                    b    += __shfl_xor_sync(0xFFFFFFFF, b, off);
                }
                if (lane == 0) {
                    float bgw = 1.f - wsum;
                    out[ray*3+0] = r + bgw;
                    out[ray*3+1] = g + bgw;
                    out[ray*3+2] = b + bgw;
                    out[4096*3 + ray] = dsum;
                    out[4096*4 + ray] = fminf(fmaxf(wsum, 1e-12f), 1000.f);
                }
            }
        } else {
            // warps 4-31: next-ray posenc (into XF region, dead since [4])
            if (ray + G < 4096)
                posenc_phase(tid, sb, dirs, rsets + (it+1)*8);
        }
        CP_WAIT(0);                    // P1(next) landed
        __syncthreads();               // [1] -> next iteration
    }
}

// ===================== launch =====================
extern "C" void kernel_launch(void* const* d_in, const int* in_sizes, int n_in,
                              void* d_out, int out_size) {
    const float* rays_o = (const float*)d_in[0];
    const float* rays_d = (const float*)d_in[1];
    const float* W1  = (const float*)d_in[2];
    const float* b1  = (const float*)d_in[3];
    const float* W2  = (const float*)d_in[4];
    const float* b2  = (const float*)d_in[5];
    const float* W3  = (const float*)d_in[6];
    const float* b3  = (const float*)d_in[7];
    const float* Wc1 = (const float*)d_in[8];
    const float* bc1 = (const float*)d_in[9];
    const float* Wc2 = (const float*)d_in[10];
    const float* bc2 = (const float*)d_in[11];
    float* out = (float*)d_out;

    prep_pack<<<84, 256>>>(W1, W2, W3);
    cudaFuncSetAttribute(nerf_mma, cudaFuncAttributeMaxDynamicSharedMemorySize, SMEM_BYTES);
    nerf_mma<<<148, 1024, SMEM_BYTES>>>(rays_o, rays_d, b1, b2, b3,
                                        Wc1, bc1, Wc2, bc2, out);
}

// round 17
// speedup vs baseline: 1.0779x; 1.0049x over previous
#include <cuda_runtime.h>
#include <cuda_bf16.h>
#include <math.h>
#include <stdint.h>

// ===================== asm helpers =====================
__device__ __forceinline__ uint32_t smem_u32(const void* p) {
    uint32_t a;
    asm("{ .reg .u64 t; cvta.to.shared.u64 t, %1; cvt.u32.u64 %0, t; }" : "=r"(a) : "l"(p));
    return a;
}
#define CP16(dst_u32, src_ptr) \
    asm volatile("cp.async.cg.shared.global [%0], [%1], 16;" :: "r"(dst_u32), "l"(src_ptr) : "memory")
#define CP_COMMIT() asm volatile("cp.async.commit_group;" ::: "memory")
#define CP_WAIT(n)  asm volatile("cp.async.wait_group %0;" :: "n"(n) : "memory")

#define MMA(d, a0, a1, a2, a3, b0, b1) \
    asm("mma.sync.aligned.m16n8k16.row.col.f32.bf16.bf16.f32 " \
        "{%0,%1,%2,%3}, {%4,%5,%6,%7}, {%8,%9}, {%0,%1,%2,%3};" \
        : "+f"((d)[0]), "+f"((d)[1]), "+f"((d)[2]), "+f"((d)[3]) \
        : "r"(a0), "r"(a1), "r"(a2), "r"(a3), "r"(b0), "r"(b1))

// X pair-layout stride (u32): 136 -> conflict-free posenc stores + A-frag loads
#define XS 136

// ===================== smem layout (persistent) =====================
#define SM_P2    0          // 131072  W2 fragments (resident)
#define SM_P3    131072     // 8192    W3 fragments (resident)
#define SM_ACT   139264     // 65536   per-ray region:
                            //  A: P1(0..32768) | XF pairs [32][136]u32 (32768..50176)
                            //  B: H1F (0..65536)
#define SM_B1    204800     // 1024
#define SM_B2    205824     // 1024
#define SM_B3    206848     // 64
#define SM_DIR   206912     // 128
#define SM_BC2   207040     // 16
#define SM_WC1   207056     // 10752 (resident)
#define SM_WC2   217808     // 768
#define SM_BC1   218576     // 256
#define SM_DIRC  218832     // 256   dircontrib[64]
#define SM_RSET  219088     // 896   ray setups [28][8] fp32
#define SM_GEOS  219984     // 8448  [16][132] fp32 transposed (outside ACT)
#define SM_ACCR  228432     // 512
#define SM_ACCG  228944     // 512
#define SM_ACCB  229456     // 512
#define SM_COMP  229968     // 2112  comp transposed [4][132] fp32
#define SMEM_BYTES 232080

#define ACT_XF    32768
#define ZERO_FLOATS 2496    // GEOS (2112) + ACCR/G/B (384), contiguous from SM_GEOS

// packed weight image (bf16 fragment order, uint4-paired): P1 32KB | P2 128KB | P3 8KB
__device__ __align__(128) uint32_t g_pack[43008];

__device__ __forceinline__ uint32_t bf16_pack2(float x, float y) {
    __nv_bfloat16 hx = __float2bfloat16(x), hy = __float2bfloat16(y);
    return (uint32_t)__bfloat16_as_ushort(hx) | ((uint32_t)__bfloat16_as_ushort(hy) << 16);
}
__device__ __forceinline__ void sts_bf16(uint32_t addr, float v) {
    uint16_t u = __bfloat16_as_ushort(__float2bfloat16(v));
    asm volatile("st.shared.u16 [%0], %1;" :: "r"(addr), "h"(u));
}
__device__ __forceinline__ void sincos_fast(float phi, float* s, float* c) {
    float k = rintf(phi * 0.15915494309f);
    float r = fmaf(-k, 6.2831854820251465f, phi);
    r = fmaf(-k, -1.7484556000744263e-07f, r);
    *s = __sinf(r);
    *c = __cosf(r);
}

// ray setup: normalize dir, AABB near/far
__device__ __forceinline__ void ray_setup(const float* __restrict__ rays_o,
                                          const float* __restrict__ rays_d, int ray,
                                          float* ox, float* oy, float* oz,
                                          float* dx, float* dy, float* dz,
                                          float* near_t, float* dtv) {
    float o0 = rays_o[ray*3+0], o1 = rays_o[ray*3+1], o2 = rays_o[ray*3+2];
    float rdx = rays_d[ray*3+0], rdy = rays_d[ray*3+1], rdz = rays_d[ray*3+2];
    float inv_norm = rsqrtf(rdx*rdx + rdy*rdy + rdz*rdz);
    float d0 = rdx*inv_norm, d1 = rdy*inv_norm, d2 = rdz*inv_norm;
    float dd;
    dd = (fabsf(d0) < 1e-8f) ? 1e-8f : d0; float i0 = __fdividef(1.0f, dd);
    dd = (fabsf(d1) < 1e-8f) ? 1e-8f : d1; float i1 = __fdividef(1.0f, dd);
    dd = (fabsf(d2) < 1e-8f) ? 1e-8f : d2; float i2 = __fdividef(1.0f, dd);
    float t0x=(-1.f-o0)*i0, t1x=(1.f-o0)*i0;
    float t0y=(-1.f-o1)*i1, t1y=(1.f-o1)*i1;
    float t0z=(-1.f-o2)*i2, t1z=(1.f-o2)*i2;
    float nx=fminf(t0x,t1x), fx=fmaxf(t0x,t1x);
    float ny=fminf(t0y,t1y), fy=fmaxf(t0y,t1y);
    float nz=fminf(t0z,t1z), fz=fmaxf(t0z,t1z);
    float nt = fmaxf(fmaxf(nx, fmaxf(ny, nz)), 0.02f);
    float ft = fminf(fmaxf(fx, fmaxf(fy, fz)), 1000.f);
    ft = fmaxf(ft, nt + 0.001f);
    *ox = o0; *oy = o1; *oz = o2; *dx = d0; *dy = d1; *dz = d2;
    *near_t = nt; *dtv = (ft - nt) * (1.0f/128.0f);
}

// posenc into XF pair layout [pair][XS] (conflict-free stores); tid in [128,1024)
__device__ __forceinline__ void posenc_phase(int tid, uint32_t sb, float* dirs,
                                             const float* rs) {
    const int m = tid & 127;
    const int gg = (tid >> 7) - 1;      // 0..6
    float ox = rs[0], oy = rs[1], oz = rs[2];
    float dx = rs[3], dy = rs[4], dz = rs[5];
    float near_t = rs[6], dtv = rs[7];
    float t = near_t + ((float)m + 0.5f) * dtv;
    float px = ox + t*dx, py = oy + t*dy, pz = oz + t*dz;
    const uint32_t xbase = sb + SM_ACT + ACT_XF;
    if (gg < 6) {
        int ci = gg >> 1, half = gg & 1;
        float pv = (ci == 0) ? px : ((ci == 1) ? py : pz);
        float f = half ? 32.f : 1.f;
        #pragma unroll
        for (int q = 0; q < 5; q++) {
            int qq = half*5 + q;
            float s, c;
            sincos_fast(pv * f, &s, &c);
            int j1 = 3 + ci*10 + qq, j2 = 33 + ci*10 + qq;
            sts_bf16(xbase + (uint32_t)(((j1 >> 1)*XS + m)*4 + (j1 & 1)*2), s);
            sts_bf16(xbase + (uint32_t)(((j2 >> 1)*XS + m)*4 + (j2 & 1)*2), c);
            f *= 2.f;
        }
    } else {
        // pair 0 = (px, py); pair 1 lo = pz; pair 31 hi = pad 0
        asm volatile("st.shared.b32 [%0], %1;" :: "r"(xbase + (uint32_t)((0*XS + m)*4)),
                     "r"(bf16_pack2(px, py)) : "memory");
        sts_bf16(xbase + (uint32_t)((1*XS + m)*4), pz);
        sts_bf16(xbase + (uint32_t)((31*XS + m)*4 + 2), 0.f);
        if (m < 27) {
            int j = m;
            float dv[3] = {dx, dy, dz};
            float v;
            if (j < 3) v = dv[j];
            else if (j < 15) { int jj = j-3;  float s,c; sincos_fast(dv[jj>>2]*(float)(1<<(jj&3)), &s, &c); v = s; }
            else             { int jj = j-15; float s,c; sincos_fast(dv[jj>>2]*(float)(1<<(jj&3)), &s, &c); v = c; }
            dirs[j] = v;
        }
    }
}

// ===================== prep: pack weights, N-tile pairs per uint4 =====================
__global__ void prep_pack(const float* __restrict__ W1, const float* __restrict__ W2,
                          const float* __restrict__ W3) {
    int s = blockIdx.x * 256 + threadIdx.x;
    if (s >= 21504) return;
    int lane = s & 31;
    int qn = lane >> 2, qk = (lane & 3) * 2;
    const float* W; int kbase, n, ldn, kmax; uint32_t base, idx;
    if (s < 4096) {                       // P1: 4 kt x 32 nt
        int t = s >> 5;
        int kt = t >> 5, nt = t & 31;
        kbase = kt * 16; n = nt * 8 + qn; W = W1; ldn = 256; kmax = 63;
        base = 0; idx = (uint32_t)(((kt * 16 + (nt >> 1)) * 32 + lane) * 4 + (nt & 1) * 2);
    } else if (s < 20480) {               // P2: 16 kt x 32 nt
        int t = (s - 4096) >> 5;
        int kt = t >> 5, nt = t & 31;
        kbase = kt * 16; n = nt * 8 + qn; W = W2; ldn = 256; kmax = 256;
        base = 8192; idx = (uint32_t)(((kt * 16 + (nt >> 1)) * 32 + lane) * 4 + (nt & 1) * 2);
    } else {                              // P3: 16 kt x 2 nt
        int t = (s - 20480) >> 5;
        int kt = t >> 1, nt = t & 1;
        kbase = kt * 16; n = nt * 8 + qn; W = W3; ldn = 16; kmax = 256;
        base = 40960; idx = (uint32_t)((kt * 32 + lane) * 4 + nt * 2);
    }
    int k0 = kbase + qk;
    float e0 = (k0     < kmax) ? W[(k0)     * ldn + n] : 0.f;
    float e1 = (k0 + 1 < kmax) ? W[(k0 + 1) * ldn + n] : 0.f;
    float e2 = (k0 + 8 < kmax) ? W[(k0 + 8) * ldn + n] : 0.f;
    float e3 = (k0 + 9 < kmax) ? W[(k0 + 9) * ldn + n] : 0.f;
    g_pack[base + idx]     = bf16_pack2(e0, e1);
    g_pack[base + idx + 1] = bf16_pack2(e2, e3);
}

// ===================== main kernel: persistent, 148 CTAs x 1024 thr =====================
__global__ void __launch_bounds__(1024, 1)
nerf_mma(const float* __restrict__ rays_o, const float* __restrict__ rays_d,
         const float* __restrict__ b1, const float* __restrict__ b2,
         const float* __restrict__ b3,
         const float* __restrict__ Wc1, const float* __restrict__ bc1,
         const float* __restrict__ Wc2, const float* __restrict__ bc2,
         float* __restrict__ out)
{
    extern __shared__ char smem[];
    const int tid  = threadIdx.x;
    const int lane = tid & 31;
    const int w    = tid >> 5;
    const int mt   = w & 3;               // M-tile (32 rows)
    const int nq   = w >> 2;              // N-eighth (32 cols)
    const int la3  = lane & 3;
    const int qk   = la3 * 2;
    const int r0   = mt * 32 + (lane >> 2);
    const int G    = gridDim.x;

    const uint32_t sb = smem_u32(smem);
    float* b1s  = (float*)(smem + SM_B1);
    float* b2s  = (float*)(smem + SM_B2);
    float* b3s  = (float*)(smem + SM_B3);
    float* dirs = (float*)(smem + SM_DIR);
    float* compT= (float*)(smem + SM_COMP);   // [4][132]
    float* bc2s = (float*)(smem + SM_BC2);
    float* dc   = (float*)(smem + SM_DIRC);
    float* rsets= (float*)(smem + SM_RSET);   // [28][8]
    float* geosf= (float*)(smem + SM_GEOS);   // [16][132]
    float* accR = (float*)(smem + SM_ACCR);
    float* accG = (float*)(smem + SM_ACCG);
    float* accB = (float*)(smem + SM_ACCB);
    const uint32_t* Xu = (const uint32_t*)(smem + SM_ACT + ACT_XF);
    const uint4* P1q = (const uint4*)(smem + SM_ACT);
    const uint4* P2q = (const uint4*)(smem + SM_P2);
    const uint4* P3q = (const uint4*)(smem + SM_P3);
    const char* gp = (const char*)g_pack;

    // ---- resident staging (once per CTA): P2, P3, color weights, P1(first) ----
    {
        uint32_t d2 = sb + SM_P2, d3 = sb + SM_P3;
        #pragma unroll
        for (int j = 0; j < 8; j++)
            CP16(d2 + (uint32_t)(tid + j * 1024) * 16, gp + 32768 + (tid + j * 1024) * 16);
        if (tid < 512) CP16(d3 + (uint32_t)tid * 16, gp + 163840 + tid * 16);
        if (tid < 672) CP16(sb + SM_WC1 + (uint32_t)tid*16, (const char*)Wc1 + tid*16);
        if (tid < 48)  CP16(sb + SM_WC2 + (uint32_t)tid*16, (const char*)Wc2 + tid*16);
        if (tid < 16)  CP16(sb + SM_BC1 + (uint32_t)tid*16, (const char*)bc1 + tid*16);
        CP_COMMIT();
        CP16(sb + SM_ACT + (uint32_t)tid * 16,          gp + tid * 16);
        CP16(sb + SM_ACT + (uint32_t)(tid + 1024) * 16, gp + (tid + 1024) * 16);
        CP_COMMIT();
    }
    if (tid < 256) { b1s[tid] = b1[tid]; b2s[tid] = b2[tid]; }
    if (tid < 16) b3s[tid] = b3[tid];
    if (tid < 3)  bc2s[tid] = bc2[tid];

    // ---- per-CTA ray-setup cache ----
    if (tid < 28) {
        int r = blockIdx.x + tid * G;
        if (r < 4096) {
            float ox, oy, oz, dx, dy, dz, nt, dt;
            ray_setup(rays_o, rays_d, r, &ox,&oy,&oz,&dx,&dy,&dz,&nt,&dt);
            float* rs = rsets + tid * 8;
            rs[0]=ox; rs[1]=oy; rs[2]=oz; rs[3]=dx; rs[4]=dy; rs[5]=dz; rs[6]=nt; rs[7]=dt;
        }
    }
    __syncthreads();

    // prologue posenc for first ray (warps 4-31)
    if (tid >= 128) posenc_phase(tid, sb, dirs, rsets);
    CP_WAIT(0);
    __syncthreads();

    int it = 0;
    for (int ray = blockIdx.x; ray < 4096; ray += G, it++) {

        // ---------------- phase 1: Layer 1 MMAs + zero GEOS/ACC (hidden) --------
        #pragma unroll
        for (int i = tid; i < ZERO_FLOATS; i += 1024)
            geosf[i] = 0.f;

        float acc[2][4][4];
        #pragma unroll
        for (int rb = 0; rb < 2; rb++)
            #pragma unroll
            for (int ct = 0; ct < 4; ct++)
                #pragma unroll
                for (int j = 0; j < 4; j++) acc[rb][ct][j] = 0.f;
        #pragma unroll
        for (int kt = 0; kt < 4; kt++) {
            int pb0 = kt*8 + la3;
            uint32_t af[2][4];
            #pragma unroll
            for (int rb = 0; rb < 2; rb++) {
                int rr = r0 + rb*16;
                af[rb][0] = Xu[pb0*XS + rr];
                af[rb][1] = Xu[pb0*XS + rr + 8];
                af[rb][2] = Xu[(pb0+4)*XS + rr];
                af[rb][3] = Xu[(pb0+4)*XS + rr + 8];
            }
            uint4 p0 = P1q[(kt*16 + nq*2)*32 + lane];
            uint4 p1 = P1q[(kt*16 + nq*2 + 1)*32 + lane];
            #pragma unroll
            for (int rb = 0; rb < 2; rb++) {
                MMA(acc[rb][0], af[rb][0], af[rb][1], af[rb][2], af[rb][3], p0.x, p0.y);
                MMA(acc[rb][1], af[rb][0], af[rb][1], af[rb][2], af[rb][3], p0.z, p0.w);
                MMA(acc[rb][2], af[rb][0], af[rb][1], af[rb][2], af[rb][3], p1.x, p1.y);
                MMA(acc[rb][3], af[rb][0], af[rb][1], af[rb][2], af[rb][3], p1.z, p1.w);
            }
        }
        __syncthreads();               // [B1] XF/P1 reads done

        // ---------------- phase 2: epilogue H1 -> A-fragment layout; dc ----------
        #pragma unroll
        for (int ct = 0; ct < 4; ct++) {
            int n0 = nq*32 + ct*8 + qk;
            float2 bb = *(const float2*)(b1s + n0);
            int kt = nq*2 + (ct >> 1);
            int j0 = (ct & 1) * 2;
            #pragma unroll
            for (int rb = 0; rb < 2; rb++) {
                uint32_t v0 = bf16_pack2(fmaxf(acc[rb][ct][0] + bb.x, 0.f), fmaxf(acc[rb][ct][1] + bb.y, 0.f));
                uint32_t v1 = bf16_pack2(fmaxf(acc[rb][ct][2] + bb.x, 0.f), fmaxf(acc[rb][ct][3] + bb.y, 0.f));
                uint32_t idx = (uint32_t)((((kt*4 + mt)*2 + rb)*32 + lane)*4 + j0);
                *(uint2*)(smem + SM_ACT + idx*4) = make_uint2(v0, v1);
            }
        }
        if (tid < 64) {   // dir contribution (ray-constant; dirs ready since prior tail)
            int j = tid;
            const float* wc1s = (const float*)(smem + SM_WC1);
            const float* bc1s = (const float*)(smem + SM_BC1);
            float h = bc1s[j];
            #pragma unroll
            for (int i = 0; i < 27; i++)
                h = fmaf(dirs[i], wc1s[i*64 + j], h);
            dc[j] = h;
        }
        __syncthreads();               // [B2]

        // ---------------- phase 3: Layer 2 MMAs + fused Layer 3 + atomics --------
        #pragma unroll
        for (int rb = 0; rb < 2; rb++)
            #pragma unroll
            for (int ct = 0; ct < 4; ct++)
                #pragma unroll
                for (int j = 0; j < 4; j++) acc[rb][ct][j] = 0.f;
        {
            const uint4* pA = (const uint4*)(smem + SM_ACT) + mt*64 + lane;
            #pragma unroll
            for (int kt = 0; kt < 16; kt++) {
                uint4 a0 = pA[kt*256];
                uint4 a1 = pA[kt*256 + 32];
                uint4 p0 = P2q[(kt*16 + nq*2)*32 + lane];
                uint4 p1 = P2q[(kt*16 + nq*2 + 1)*32 + lane];
                MMA(acc[0][0], a0.x, a0.y, a0.z, a0.w, p0.x, p0.y);
                MMA(acc[0][1], a0.x, a0.y, a0.z, a0.w, p0.z, p0.w);
                MMA(acc[0][2], a0.x, a0.y, a0.z, a0.w, p1.x, p1.y);
                MMA(acc[0][3], a0.x, a0.y, a0.z, a0.w, p1.z, p1.w);
                MMA(acc[1][0], a1.x, a1.y, a1.z, a1.w, p0.x, p0.y);
                MMA(acc[1][1], a1.x, a1.y, a1.z, a1.w, p0.z, p0.w);
                MMA(acc[1][2], a1.x, a1.y, a1.z, a1.w, p1.x, p1.y);
                MMA(acc[1][3], a1.x, a1.y, a1.z, a1.w, p1.z, p1.w);
            }
        }
        // fused Layer 3: register-only dependency on acc — no barrier needed
        {
            float geo[2][2][4];
            #pragma unroll
            for (int rb = 0; rb < 2; rb++)
                #pragma unroll
                for (int nt = 0; nt < 2; nt++)
                    #pragma unroll
                    for (int j = 0; j < 4; j++) geo[rb][nt][j] = 0.f;
            #pragma unroll
            for (int ii = 0; ii < 2; ii++) {
                int kt3 = nq*2 + ii;
                uint4 bq = P3q[kt3*32 + lane];
                int n0 = nq*32 + (2*ii)*8 + qk;
                float2 bb0 = *(const float2*)(b2s + n0);
                float2 bb1 = *(const float2*)(b2s + n0 + 8);
                #pragma unroll
                for (int rb = 0; rb < 2; rb++) {
                    uint32_t a0 = bf16_pack2(fmaxf(acc[rb][2*ii][0] + bb0.x, 0.f),  fmaxf(acc[rb][2*ii][1] + bb0.y, 0.f));
                    uint32_t a1 = bf16_pack2(fmaxf(acc[rb][2*ii][2] + bb0.x, 0.f),  fmaxf(acc[rb][2*ii][3] + bb0.y, 0.f));
                    uint32_t a2 = bf16_pack2(fmaxf(acc[rb][2*ii+1][0] + bb1.x, 0.f), fmaxf(acc[rb][2*ii+1][1] + bb1.y, 0.f));
                    uint32_t a3 = bf16_pack2(fmaxf(acc[rb][2*ii+1][2] + bb1.x, 0.f), fmaxf(acc[rb][2*ii+1][3] + bb1.y, 0.f));
                    MMA(geo[rb][0], a0, a1, a2, a3, bq.x, bq.y);
                    MMA(geo[rb][1], a0, a1, a2, a3, bq.z, bq.w);
                }
            }
            #pragma unroll
            for (int rb = 0; rb < 2; rb++)
                #pragma unroll
                for (int nt = 0; nt < 2; nt++) {
                    int c = nt*8 + qk;
                    int rr = r0 + rb*16;
                    atomicAdd(&geosf[c*132 + rr],       geo[rb][nt][0]);
                    atomicAdd(&geosf[(c+1)*132 + rr],   geo[rb][nt][1]);
                    atomicAdd(&geosf[c*132 + rr + 8],   geo[rb][nt][2]);
                    atomicAdd(&geosf[(c+1)*132 + rr+8], geo[rb][nt][3]);
                }
        }
        __syncthreads();               // [B3] H1F reads + geosf atomics done

        // ---------------- phase 4: P1(next) stage + color ----------------
        CP16(sb + SM_ACT + (uint32_t)tid * 16,          gp + tid * 16);
        CP16(sb + SM_ACT + (uint32_t)(tid + 1024) * 16, gp + (tid + 1024) * 16);
        CP_COMMIT();
        {
            const float* wc1s = (const float*)(smem + SM_WC1);
            const float* wc2s = (const float*)(smem + SM_WC2);
            const int m = tid & 127, g = tid >> 7;
            float fea[15];
            #pragma unroll
            for (int i = 0; i < 15; i++) fea[i] = geosf[(1+i)*132 + m] + b3s[1+i];
            float a0 = 0.f, a1 = 0.f, a2 = 0.f;
            const int j0 = g * 8;
            #pragma unroll
            for (int jj = 0; jj < 8; jj++) {
                int j = j0 + jj;
                float h = dc[j];
                #pragma unroll
                for (int i = 0; i < 15; i++)
                    h = fmaf(fea[i], wc1s[(27+i)*64 + j], h);
                h = fmaxf(h, 0.f);
                a0 = fmaf(h, wc2s[j*3+0], a0);
                a1 = fmaf(h, wc2s[j*3+1], a1);
                a2 = fmaf(h, wc2s[j*3+2], a2);
            }
            atomicAdd(&accR[m], a0);
            atomicAdd(&accG[m], a1);
            atomicAdd(&accB[m], a2);
        }
        __syncthreads();               // [B4]

        // ---------------- phase 5: split tail ----------------
        if (tid < 128) {
            const float* rs = rsets + it*8;
            float near_t = rs[6], dtv = rs[7];
            int m = tid;
            float a0 = accR[m] + bc2s[0];
            float a1 = accG[m] + bc2s[1];
            float a2 = accB[m] + bc2s[2];
            float sx = geosf[0*132 + m] + b3s[0];
            float sigma = (sx > 20.f) ? sx : log1pf(__expf(sx));
            float alpha = 1.f - __expf(-sigma * dtv);
            compT[0*132 + m] = alpha;
            compT[1*132 + m] = 1.f / (1.f + __expf(-a0));
            compT[2*132 + m] = 1.f / (1.f + __expf(-a1));
            compT[3*132 + m] = 1.f / (1.f + __expf(-a2));
            asm volatile("bar.sync 1, 128;" ::: "memory");
            if (tid < 32) {
                float4 av = *(const float4*)(compT + 0*132 + lane*4);
                float4 rv = *(const float4*)(compT + 1*132 + lane*4);
                float4 gv = *(const float4*)(compT + 2*132 + lane*4);
                float4 bv = *(const float4*)(compT + 3*132 + lane*4);
                float q0 = 1.f - av.x + 1e-10f;
                float q1 = 1.f - av.y + 1e-10f;
                float q2 = 1.f - av.z + 1e-10f;
                float q3 = 1.f - av.w + 1e-10f;
                float inc = ((q0*q1)*(q2*q3));
                #pragma unroll
                for (int off = 1; off < 32; off <<= 1) {
                    float t = __shfl_up_sync(0xFFFFFFFF, inc, off);
                    if (lane >= off) inc *= t;
                }
                float T = __shfl_up_sync(0xFFFFFFFF, inc, 1);
                if (lane == 0) T = 1.f;
                float alp[4] = {av.x, av.y, av.z, av.w};
                float rr[4] = {rv.x, rv.y, rv.z, rv.w};
                float gg[4] = {gv.x, gv.y, gv.z, gv.w};
                float bb[4] = {bv.x, bv.y, bv.z, bv.w};
                float wsum = 0.f, dsum = 0.f, r = 0.f, g = 0.f, b = 0.f;
                #pragma unroll
                for (int j = 0; j < 4; j++) {
                    int mm = lane*4 + j;
                    float wgt = (T > 1e-4f) ? alp[j] * T : 0.f;
                    wsum += wgt;
                    float tsv = near_t + ((float)mm + 0.5f) * dtv;
                    dsum = fmaf(wgt, tsv, dsum);
                    r = fmaf(wgt, rr[j], r);
                    g = fmaf(wgt, gg[j], g);
                    b = fmaf(wgt, bb[j], b);
                    T *= (1.f - alp[j] + 1e-10f);
                }
                #pragma unroll
                for (int off = 16; off > 0; off >>= 1) {
                    wsum += __shfl_xor_sync(0xFFFFFFFF, wsum, off);
                    dsum += __shfl_xor_sync(0xFFFFFFFF, dsum, off);
                    r    += __shfl_xor_sync(0xFFFFFFFF, r, off);
                    g    += __shfl_xor_sync(0xFFFFFFFF, g, off);
                    b    += __shfl_xor_sync(0xFFFFFFFF, b, off);
                }
                if (lane == 0) {
                    float bgw = 1.f - wsum;
                    out[ray*3+0] = r + bgw;
                    out[ray*3+1] = g + bgw;
                    out[ray*3+2] = b + bgw;
                    out[4096*3 + ray] = dsum;
                    out[4096*4 + ray] = fminf(fmaxf(wsum, 1e-12f), 1000.f);
                }
            }
        } else {
            // warps 4-31: next-ray posenc (into XF region, dead since [B3])
            if (ray + G < 4096)
                posenc_phase(tid, sb, dirs, rsets + (it+1)*8);
        }
        CP_WAIT(0);                    // P1(next) landed
        __syncthreads();               // [B5] -> next iteration
    }
}

// ===================== launch =====================
extern "C" void kernel_launch(void* const* d_in, const int* in_sizes, int n_in,
                              void* d_out, int out_size) {
    const float* rays_o = (const float*)d_in[0];
    const float* rays_d = (const float*)d_in[1];
    const float* W1  = (const float*)d_in[2];
    const float* b1  = (const float*)d_in[3];
    const float* W2  = (const float*)d_in[4];
    const float* b2  = (const float*)d_in[5];
    const float* W3  = (const float*)d_in[6];
    const float* b3  = (const float*)d_in[7];
    const float* Wc1 = (const float*)d_in[8];
    const float* bc1 = (const float*)d_in[9];
    const float* Wc2 = (const float*)d_in[10];
    const float* bc2 = (const float*)d_in[11];
    float* out = (float*)d_out;

    prep_pack<<<84, 256>>>(W1, W2, W3);
    cudaFuncSetAttribute(nerf_mma, cudaFuncAttributeMaxDynamicSharedMemorySize, SMEM_BYTES);
    nerf_mma<<<148, 1024, SMEM_BYTES>>>(rays_o, rays_d, b1, b2, b3,
                                        Wc1, bc1, Wc2, bc2, out);
}